// round 1
// baseline (speedup 1.0000x reference)
#include <cuda_runtime.h>
#include <cuda_bf16.h>
#include <cstdio>

// ---------------------------------------------------------------------------
// GraphEncoder baseline: fp32 tiled GEMM + fused elementwise kernels.
// Shapes: B=16, S=1024 (segments 512/256/256), H=256, heads=4 (Dh=64), F=400.
// ---------------------------------------------------------------------------

#define NB 16
#define SEQ 1024
#define HID 256
#define NHEADS 4
#define DH 64
#define FF 400
#define TOKENS (NB * SEQ)   // 16384

// scores buffer: per segment, 16*4*L*L
#define SC0 0L
#define SC1 ((long)16 * 4 * 512 * 512)                 // 16777216
#define SC2 (SC1 + (long)16 * 4 * 256 * 256)           // 20971520
#define SC_TOTAL (SC2 + (long)16 * 4 * 256 * 256)      // 25165824

// -------------------- scratch (device globals; no allocation) --------------
__device__ float g_h0[TOKENS * HID];        // gather out
__device__ float g_t[TOKENS * HID];         // generic temp (H wide)
__device__ float g_x[TOKENS * HID];         // main activation
__device__ float g_x1[TOKENS * HID];        // post-LN1 activation
__device__ float g_qkv[TOKENS * 3 * HID];   // qkv
__device__ float g_sc[SC_TOTAL];            // attention scores
__device__ float g_ctx[TOKENS * HID];       // attention context
__device__ float g_ff[TOKENS * FF];         // FF hidden
__device__ float g_mean[NB * 3 * HID];      // segment means

// -------------------- generic strided-batched SGEMM ------------------------
// C[m,n] = alpha * sum_k A[m,k] * (transB ? B[n,k] : B[k,n]) (+bias[n]) (relu?)
// z = blockIdx.z decomposed into (batch, head) via nheads; per-axis strides.
#define BM 128
#define BN 128
#define BKK 8
#define TM 8
#define TN 8

__global__ void __launch_bounds__(256) gemm_k(
    const float* __restrict__ A, const float* __restrict__ Bm,
    const float* __restrict__ bias, float* __restrict__ C,
    int M, int N, int K, int lda, int ldb, int ldc,
    long sAb, long sAh, long sBb, long sBh, long sCb, long sCh,
    int nheads, float alpha, int flags)   // flags bit0: transB, bit1: relu
{
    int z  = blockIdx.z;
    int bb = z / nheads, hh = z % nheads;
    A  += (long)bb * sAb + (long)hh * sAh;
    Bm += (long)bb * sBb + (long)hh * sBh;
    C  += (long)bb * sCb + (long)hh * sCh;

    __shared__ float As[BKK][BM];
    __shared__ float Bs[BKK][BN + 4];

    const int tid = threadIdx.x;
    const int tx = tid & 15, ty = tid >> 4;
    const int rowTile = blockIdx.y * BM;
    const int colTile = blockIdx.x * BN;

    const int ar = tid >> 1;          // 0..127
    const int ac = (tid & 1) * 4;     // 0 or 4
    const int br = tid >> 5;          // 0..7
    const int bc = (tid & 31) * 4;    // 0..124

    const bool transB = flags & 1;

    float acc[TM][TN];
#pragma unroll
    for (int i = 0; i < TM; i++)
#pragma unroll
        for (int j = 0; j < TN; j++) acc[i][j] = 0.f;

    for (int k0 = 0; k0 < K; k0 += BKK) {
        // load A tile (BM x BKK), transposed into As[k][m]; K % 8 == 0 always
        {
            int m = rowTile + ar;
#pragma unroll
            for (int i = 0; i < 4; i++) {
                float v = 0.f;
                if (m < M) v = A[(long)m * lda + (k0 + ac + i)];
                As[ac + i][ar] = v;
            }
        }
        // load B tile
        if (!transB) {
            int kk = k0 + br;
#pragma unroll
            for (int i = 0; i < 4; i++) {
                int n = colTile + bc + i;
                float v = 0.f;
                if (n < N) v = Bm[(long)kk * ldb + n];
                Bs[br][bc + i] = v;
            }
        } else {
            int n = colTile + ar;
#pragma unroll
            for (int i = 0; i < 4; i++) {
                float v = 0.f;
                if (n < N) v = Bm[(long)n * ldb + (k0 + ac + i)];
                Bs[ac + i][ar] = v;
            }
        }
        __syncthreads();

#pragma unroll
        for (int kk = 0; kk < BKK; kk++) {
            float a[TM], b[TN];
#pragma unroll
            for (int i = 0; i < TM; i++) a[i] = As[kk][ty * TM + i];
#pragma unroll
            for (int j = 0; j < TN; j++) b[j] = Bs[kk][tx * TN + j];
#pragma unroll
            for (int i = 0; i < TM; i++)
#pragma unroll
                for (int j = 0; j < TN; j++) acc[i][j] += a[i] * b[j];
        }
        __syncthreads();
    }

    const bool relu = flags & 2;
#pragma unroll
    for (int i = 0; i < TM; i++) {
        int m = rowTile + ty * TM + i;
        if (m >= M) continue;
#pragma unroll
        for (int j = 0; j < TN; j++) {
            int n = colTile + tx * TN + j;
            if (n >= N) continue;
            float v = acc[i][j] * alpha;
            if (bias) v += bias[n];
            if (relu) v = fmaxf(v, 0.f);
            C[(long)m * ldc + n] = v;
        }
    }
}

// -------------------- embedding gather -------------------------------------
__global__ void gather_k(const int* __restrict__ idx,
                         const float* __restrict__ tab,
                         float* __restrict__ out)
{
    long tok = blockIdx.x;
    int id = idx[tok];
    const float4* src = (const float4*)(tab + (long)id * HID);
    float4* dst = (float4*)(out + tok * HID);
    dst[threadIdx.x] = src[threadIdx.x];   // 64 threads * float4 = 256 floats
}

// -------------------- row softmax (in place) -------------------------------
__global__ void softmax_k(float* __restrict__ sc, int L)
{
    long row = blockIdx.x;
    float* p = sc + row * (long)L;
    int t = threadIdx.x;              // 256
    __shared__ float red[256];

    float m = -1e30f;
    for (int i = t; i < L; i += 256) m = fmaxf(m, p[i]);
    red[t] = m; __syncthreads();
    for (int s = 128; s > 0; s >>= 1) { if (t < s) red[t] = fmaxf(red[t], red[t + s]); __syncthreads(); }
    m = red[0]; __syncthreads();

    float sum = 0.f;
    for (int i = t; i < L; i += 256) { float e = __expf(p[i] - m); p[i] = e; sum += e; }
    red[t] = sum; __syncthreads();
    for (int s = 128; s > 0; s >>= 1) { if (t < s) red[t] += red[t + s]; __syncthreads(); }
    float inv = 1.f / red[0];
    for (int i = t; i < L; i += 256) p[i] *= inv;
}

// -------------------- residual add + layernorm ------------------------------
__global__ void add_ln_k(const float* __restrict__ x, const float* __restrict__ y,
                         const float* __restrict__ g, const float* __restrict__ b,
                         float* __restrict__ out)
{
    long row = blockIdx.x;
    int t = threadIdx.x;  // 256 == HID
    __shared__ float red[256];

    float v = x[row * HID + t] + y[row * HID + t];
    red[t] = v; __syncthreads();
    for (int s = 128; s > 0; s >>= 1) { if (t < s) red[t] += red[t + s]; __syncthreads(); }
    float mu = red[0] * (1.f / HID);
    __syncthreads();
    float d = v - mu;
    red[t] = d * d; __syncthreads();
    for (int s = 128; s > 0; s >>= 1) { if (t < s) red[t] += red[t + s]; __syncthreads(); }
    float var = red[0] * (1.f / HID);
    out[row * HID + t] = d * rsqrtf(var + 1e-5f) * g[t] + b[t];
}

// -------------------- per-segment mean --------------------------------------
__global__ void mean_k(const float* __restrict__ x, float* __restrict__ mout)
{
    int b = blockIdx.x / 3, sgi = blockIdx.x % 3;
    int off = (sgi == 0) ? 0 : (sgi == 1 ? 512 : 768);
    int L   = (sgi == 0) ? 512 : 256;
    int t = threadIdx.x;
    const float* p = x + ((long)b * SEQ + off) * HID + t;
    float s = 0.f;
    for (int i = 0; i < L; i++) s += p[(long)i * HID];
    mout[(long)blockIdx.x * HID + t] = s * (1.f / L);
}

// -------------------- final: relu((p-n+f) @ W + b) --------------------------
__global__ void final_k(const float* __restrict__ mean, const float* __restrict__ W,
                        const float* __restrict__ bias, float* __restrict__ out)
{
    int b = blockIdx.x, n = threadIdx.x;
    __shared__ float comb[HID];
    const float* mp = mean + (long)b * 3 * HID;
    comb[n] = mp[n] - mp[HID + n] + mp[2 * HID + n];
    __syncthreads();
    float s = bias[n];
#pragma unroll 8
    for (int k = 0; k < HID; k++) s += comb[k] * W[k * HID + n];
    out[(long)b * HID + n] = fmaxf(s, 0.f);
}

// ---------------------------------------------------------------------------
static void launch_gemm(const float* A, const float* B, const float* bias, float* C,
                        int M, int N, int K, int lda, int ldb, int ldc,
                        long sAb, long sAh, long sBb, long sBh, long sCb, long sCh,
                        int nheads, int batches, float alpha, int flags)
{
    dim3 grid((N + BN - 1) / BN, (M + BM - 1) / BM, batches);
    gemm_k<<<grid, 256>>>(A, B, bias, C, M, N, K, lda, ldb, ldc,
                          sAb, sAh, sBb, sBh, sCb, sCh, nheads, alpha, flags);
}

extern "C" void kernel_launch(void* const* d_in, const int* in_sizes, int n_in,
                              void* d_out, int out_size)
{
    const int*   hyper = (const int*)  d_in[0];
    const float* HT    = (const float*)d_in[1];
    const float* emb   = (const float*)d_in[2];
    const float* Wg1   = (const float*)d_in[3];
    const float* bg1   = (const float*)d_in[4];
    const float* Wg2   = (const float*)d_in[5];
    const float* bg2   = (const float*)d_in[6];
    const float* Wqkv  = (const float*)d_in[7];
    const float* bqkv  = (const float*)d_in[8];
    const float* Wo    = (const float*)d_in[9];
    const float* bo    = (const float*)d_in[10];
    const float* ln1g  = (const float*)d_in[11];
    const float* ln1b  = (const float*)d_in[12];
    const float* Wff1  = (const float*)d_in[13];
    const float* bff1  = (const float*)d_in[14];
    const float* Wff2  = (const float*)d_in[15];
    const float* bff2  = (const float*)d_in[16];
    const float* ln2g  = (const float*)d_in[17];
    const float* ln2b  = (const float*)d_in[18];
    const float* fc1W  = (const float*)d_in[19];
    const float* fc1b  = (const float*)d_in[20];

    float *h0, *t, *x, *x1, *qkv, *sc, *ctx, *ff, *mean;
    cudaGetSymbolAddress((void**)&h0,   g_h0);
    cudaGetSymbolAddress((void**)&t,    g_t);
    cudaGetSymbolAddress((void**)&x,    g_x);
    cudaGetSymbolAddress((void**)&x1,   g_x1);
    cudaGetSymbolAddress((void**)&qkv,  g_qkv);
    cudaGetSymbolAddress((void**)&sc,   g_sc);
    cudaGetSymbolAddress((void**)&ctx,  g_ctx);
    cudaGetSymbolAddress((void**)&ff,   g_ff);
    cudaGetSymbolAddress((void**)&mean, g_mean);

    // 1. embedding gather
    gather_k<<<TOKENS, 64>>>(hyper, emb, h0);

    // 2. t = h0 @ Wg1
    launch_gemm(h0, Wg1, nullptr, t, TOKENS, HID, HID, HID, HID, HID,
                0, 0, 0, 0, 0, 0, 1, 1, 1.f, 0);

    // 3. x = batched HT @ t + bg1
    launch_gemm(HT, t, bg1, x, SEQ, HID, SEQ, SEQ, HID, HID,
                (long)SEQ * SEQ, 0, (long)SEQ * HID, 0, (long)SEQ * HID, 0,
                1, NB, 1.f, 0);

    // 4. t = x @ Wg2
    launch_gemm(x, Wg2, nullptr, t, TOKENS, HID, HID, HID, HID, HID,
                0, 0, 0, 0, 0, 0, 1, 1, 1.f, 0);

    // 5. x = batched HT @ t + bg2
    launch_gemm(HT, t, bg2, x, SEQ, HID, SEQ, SEQ, HID, HID,
                (long)SEQ * SEQ, 0, (long)SEQ * HID, 0, (long)SEQ * HID, 0,
                1, NB, 1.f, 0);

    // 6. qkv = x @ Wqkv + bqkv
    launch_gemm(x, Wqkv, bqkv, qkv, TOKENS, 3 * HID, HID, HID, 3 * HID, 3 * HID,
                0, 0, 0, 0, 0, 0, 1, 1, 1.f, 0);

    // 7-9. segmented attention
    const int  segoff[3] = {0, 512, 768};
    const int  seglen[3] = {512, 256, 256};
    const long scoff[3]  = {SC0, SC1, SC2};
    const float scale = 0.125f;  // 1/sqrt(64)

    for (int s = 0; s < 3; s++) {
        int off = segoff[s], L = seglen[s];
        // scores = (Q @ K^T) * scale      [z = b*4 + head]
        launch_gemm(qkv + (long)off * 3 * HID + 0,
                    qkv + (long)off * 3 * HID + HID,
                    nullptr, sc + scoff[s],
                    L, L, DH, 3 * HID, 3 * HID, L,
                    (long)SEQ * 3 * HID, DH,
                    (long)SEQ * 3 * HID, DH,
                    (long)NHEADS * L * L, (long)L * L,
                    NHEADS, NB * NHEADS, scale, /*transB*/1);
        // softmax rows
        softmax_k<<<NB * NHEADS * L, 256>>>(sc + scoff[s], L);
        // ctx = attn @ V, written into (B,S,H) layout at head column offset
        launch_gemm(sc + scoff[s],
                    qkv + (long)off * 3 * HID + 2 * HID,
                    nullptr, ctx + (long)off * HID,
                    L, DH, L, L, 3 * HID, HID,
                    (long)NHEADS * L * L, (long)L * L,
                    (long)SEQ * 3 * HID, DH,
                    (long)SEQ * HID, DH,
                    NHEADS, NB * NHEADS, 1.f, 0);
    }

    // 10. t = ctx @ Wo + bo
    launch_gemm(ctx, Wo, bo, t, TOKENS, HID, HID, HID, HID, HID,
                0, 0, 0, 0, 0, 0, 1, 1, 1.f, 0);

    // 11. x1 = LN1(x + t)
    add_ln_k<<<TOKENS, 256>>>(x, t, ln1g, ln1b, x1);

    // 12. ff = relu(x1 @ Wff1 + bff1)
    launch_gemm(x1, Wff1, bff1, ff, TOKENS, FF, HID, HID, FF, FF,
                0, 0, 0, 0, 0, 0, 1, 1, 1.f, /*relu*/2);

    // 13. t = ff @ Wff2 + bff2
    launch_gemm(ff, Wff2, bff2, t, TOKENS, HID, FF, FF, HID, HID,
                0, 0, 0, 0, 0, 0, 1, 1, 1.f, 0);

    // 14. x = LN2(x1 + t)
    add_ln_k<<<TOKENS, 256>>>(x1, t, ln2g, ln2b, x);

    // 15. per-segment means
    mean_k<<<NB * 3, 256>>>(x, mean);

    // 16. out = relu((p - n + f) @ fc1W + fc1b)
    final_k<<<NB, 256>>>(mean, fc1W, fc1b, (float*)d_out);
}

// round 2
// speedup vs baseline: 1.8787x; 1.8787x over previous
#include <cuda_runtime.h>
#include <cuda_bf16.h>
#include <mma.h>

using namespace nvcuda;

// ---------------------------------------------------------------------------
// GraphEncoder: tf32 tensor-core GEMM + fused elementwise kernels.
// Shapes: B=16, S=1024 (segments 512/256/256), H=256, heads=4 (Dh=64), F=400.
// ---------------------------------------------------------------------------

#define NB 16
#define SEQ 1024
#define HID 256
#define NHEADS 4
#define DH 64
#define FF 400
#define TOKENS (NB * SEQ)   // 16384

#define SC0 0L
#define SC1 ((long)16 * 4 * 512 * 512)
#define SC2 (SC1 + (long)16 * 4 * 256 * 256)
#define SC_TOTAL (SC2 + (long)16 * 4 * 256 * 256)

// -------------------- scratch (device globals; no allocation) --------------
__device__ float g_h0[TOKENS * HID];
__device__ float g_t[TOKENS * HID];
__device__ float g_x[TOKENS * HID];
__device__ float g_x1[TOKENS * HID];
__device__ float g_qkv[TOKENS * 3 * HID];
__device__ float g_sc[SC_TOTAL];
__device__ float g_ctx[TOKENS * HID];
__device__ float g_ff[TOKENS * FF];
__device__ float g_mean[NB * 3 * HID];

// -------------------- tf32 tensor-core GEMM --------------------------------
// C[m,n] = alpha * sum_k A[m,k] * (TRANSB ? B[n,k] : B[k,n]) (+bias[n]) (relu?)
// Requirements guaranteed by call sites: M % 128 == 0, K % 16 == 0,
// 16B alignment of all tiles. Only N needs bounds handling.
#define BM 128
#define BN 64
#define BK 16
#define APAD 20     // As row stride (floats)
#define BPADN 68    // Bs row stride, k-major (normal)
#define BPADT 20    // Bs row stride, n-major (transB)
#define EPI_LD 36
#define SMEM_FLOATS 9216  // max(2*2560 + 2*1280, 8*32*36)

__device__ __forceinline__ unsigned sptr(const void* p) {
    return (unsigned)__cvta_generic_to_shared(p);
}
#define CPA16(dst, src) asm volatile("cp.async.ca.shared.global [%0], [%1], 16;" :: "r"(dst), "l"(src))
#define CPA_COMMIT()    asm volatile("cp.async.commit_group;")
#define CPA_WAIT0()     asm volatile("cp.async.wait_group 0;")

template<int TRANSB>
__global__ void __launch_bounds__(256) gemm_tc(
    const float* __restrict__ A, const float* __restrict__ Bm,
    const float* __restrict__ bias, float* __restrict__ C,
    int M, int N, int K, int lda, int ldb, int ldc,
    long sAb, long sAh, long sBb, long sBh, long sCb, long sCh,
    int nheads, float alpha, int relu)
{
    __shared__ float smem[SMEM_FLOATS];

    const int z  = blockIdx.z;
    const int bb = z / nheads, hh = z % nheads;
    A  += (long)bb * sAb + (long)hh * sAh;
    Bm += (long)bb * sBb + (long)hh * sBh;
    C  += (long)bb * sCb + (long)hh * sCh;

    const int tid = threadIdx.x;
    const int w = tid >> 5, lane = tid & 31;
    const int wm = w & 3, wn = w >> 2;           // 4 x 2 warp grid
    const int rowTile = blockIdx.y * BM;
    const int colTile = blockIdx.x * BN;

    wmma::fragment<wmma::accumulator, 16, 16, 8, float> acc[2][2];
#pragma unroll
    for (int i = 0; i < 2; i++)
#pragma unroll
        for (int j = 0; j < 2; j++) wmma::fill_fragment(acc[i][j], 0.f);

    const int nk = K / BK;

    // ---- async tile loaders ----
    auto loadA = [&](int kt, int buf) {
        const float* Ag = A + (long)rowTile * lda + kt * BK;
        float* s = smem + buf * 2560;
#pragma unroll
        for (int i = 0; i < 2; i++) {
            int idx = tid * 2 + i;          // 0..511  (128 rows x 4 float4)
            int r = idx >> 2, c4 = (idx & 3) * 4;
            CPA16(sptr(s + r * APAD + c4), Ag + (long)r * lda + c4);
        }
    };
    auto loadB = [&](int kt, int buf) {
        float* s = smem + 5120 + buf * 1280;
        if (!TRANSB) {
            int r = tid >> 4, c4 = (tid & 15) * 4;   // 16 rows x 16 float4
            int n = colTile + c4;
            float* d = s + r * BPADN + c4;
            if (n < N) CPA16(sptr(d), Bm + (long)(kt * BK + r) * ldb + n);
            else { d[0] = 0.f; d[1] = 0.f; d[2] = 0.f; d[3] = 0.f; }
        } else {
            int r = tid >> 2, c4 = (tid & 3) * 4;    // 64 rows x 4 float4
            int n = colTile + r;
            float* d = s + r * BPADT + c4;
            if (n < N) CPA16(sptr(d), Bm + (long)n * ldb + kt * BK + c4);
            else { d[0] = 0.f; d[1] = 0.f; d[2] = 0.f; d[3] = 0.f; }
        }
    };

    loadA(0, 0); loadB(0, 0); CPA_COMMIT();

    int buf = 0;
    for (int kt = 0; kt < nk; kt++) {
        CPA_WAIT0();
        __syncthreads();
        if (kt + 1 < nk) { loadA(kt + 1, buf ^ 1); loadB(kt + 1, buf ^ 1); CPA_COMMIT(); }

        const float* As_ = smem + buf * 2560;
        const float* Bs_ = smem + 5120 + buf * 1280;

#pragma unroll
        for (int ks = 0; ks < 2; ks++) {
            wmma::fragment<wmma::matrix_a, 16, 16, 8, wmma::precision::tf32, wmma::row_major> af[2];
#pragma unroll
            for (int mi = 0; mi < 2; mi++) {
                wmma::load_matrix_sync(af[mi], As_ + (wm * 32 + mi * 16) * APAD + ks * 8, APAD);
#pragma unroll
                for (int e = 0; e < af[mi].num_elements; e++)
                    af[mi].x[e] = wmma::__float_to_tf32(af[mi].x[e]);
            }
            if (!TRANSB) {
                wmma::fragment<wmma::matrix_b, 16, 16, 8, wmma::precision::tf32, wmma::row_major> bf[2];
#pragma unroll
                for (int ni = 0; ni < 2; ni++) {
                    wmma::load_matrix_sync(bf[ni], Bs_ + (ks * 8) * BPADN + wn * 32 + ni * 16, BPADN);
#pragma unroll
                    for (int e = 0; e < bf[ni].num_elements; e++)
                        bf[ni].x[e] = wmma::__float_to_tf32(bf[ni].x[e]);
                }
#pragma unroll
                for (int mi = 0; mi < 2; mi++)
#pragma unroll
                    for (int ni = 0; ni < 2; ni++)
                        wmma::mma_sync(acc[mi][ni], af[mi], bf[ni], acc[mi][ni]);
            } else {
                wmma::fragment<wmma::matrix_b, 16, 16, 8, wmma::precision::tf32, wmma::col_major> bf[2];
#pragma unroll
                for (int ni = 0; ni < 2; ni++) {
                    wmma::load_matrix_sync(bf[ni], Bs_ + (wn * 32 + ni * 16) * BPADT + ks * 8, BPADT);
#pragma unroll
                    for (int e = 0; e < bf[ni].num_elements; e++)
                        bf[ni].x[e] = wmma::__float_to_tf32(bf[ni].x[e]);
                }
#pragma unroll
                for (int mi = 0; mi < 2; mi++)
#pragma unroll
                    for (int ni = 0; ni < 2; ni++)
                        wmma::mma_sync(acc[mi][ni], af[mi], bf[ni], acc[mi][ni]);
            }
        }
        __syncthreads();
        buf ^= 1;
    }

    // ---- epilogue via smem (bounds + alpha + bias + relu) ----
    float* ep = smem + w * 1152;   // 32 x 36 per warp
#pragma unroll
    for (int mi = 0; mi < 2; mi++)
#pragma unroll
        for (int ni = 0; ni < 2; ni++)
            wmma::store_matrix_sync(ep + (mi * 16) * EPI_LD + ni * 16, acc[mi][ni],
                                    EPI_LD, wmma::mem_row_major);
    __syncwarp();

    const int m0 = rowTile + wm * 32;
    const int n  = colTile + wn * 32 + lane;
    if (n < N) {
        float bv = bias ? bias[n] : 0.f;
#pragma unroll 4
        for (int r = 0; r < 32; r++) {
            float v = ep[r * EPI_LD + lane] * alpha + bv;
            if (relu) v = fmaxf(v, 0.f);
            C[(long)(m0 + r) * ldc + n] = v;
        }
    }
}

// -------------------- embedding gather -------------------------------------
__global__ void gather_k(const int* __restrict__ idx,
                         const float* __restrict__ tab,
                         float* __restrict__ out)
{
    long tok = blockIdx.x;
    int id = idx[tok];
    const float4* src = (const float4*)(tab + (long)id * HID);
    float4* dst = (float4*)(out + tok * HID);
    dst[threadIdx.x] = src[threadIdx.x];
}

// -------------------- row softmax (in place) -------------------------------
__global__ void softmax_k(float* __restrict__ sc, int L)
{
    long row = blockIdx.x;
    float* p = sc + row * (long)L;
    int t = threadIdx.x;              // 256
    __shared__ float red[256];

    float m = -1e30f;
    for (int i = t; i < L; i += 256) m = fmaxf(m, p[i]);
    red[t] = m; __syncthreads();
    for (int s = 128; s > 0; s >>= 1) { if (t < s) red[t] = fmaxf(red[t], red[t + s]); __syncthreads(); }
    m = red[0]; __syncthreads();

    float sum = 0.f;
    for (int i = t; i < L; i += 256) { float e = __expf(p[i] - m); p[i] = e; sum += e; }
    red[t] = sum; __syncthreads();
    for (int s = 128; s > 0; s >>= 1) { if (t < s) red[t] += red[t + s]; __syncthreads(); }
    float inv = 1.f / red[0];
    for (int i = t; i < L; i += 256) p[i] *= inv;
}

// -------------------- residual add + layernorm ------------------------------
__global__ void add_ln_k(const float* __restrict__ x, const float* __restrict__ y,
                         const float* __restrict__ g, const float* __restrict__ b,
                         float* __restrict__ out)
{
    long row = blockIdx.x;
    int t = threadIdx.x;  // 256 == HID
    __shared__ float red[256];

    float v = x[row * HID + t] + y[row * HID + t];
    red[t] = v; __syncthreads();
    for (int s = 128; s > 0; s >>= 1) { if (t < s) red[t] += red[t + s]; __syncthreads(); }
    float mu = red[0] * (1.f / HID);
    __syncthreads();
    float d = v - mu;
    red[t] = d * d; __syncthreads();
    for (int s = 128; s > 0; s >>= 1) { if (t < s) red[t] += red[t + s]; __syncthreads(); }
    float var = red[0] * (1.f / HID);
    out[row * HID + t] = d * rsqrtf(var + 1e-5f) * g[t] + b[t];
}

// -------------------- per-segment mean --------------------------------------
__global__ void mean_k(const float* __restrict__ x, float* __restrict__ mout)
{
    int b = blockIdx.x / 3, sgi = blockIdx.x % 3;
    int off = (sgi == 0) ? 0 : (sgi == 1 ? 512 : 768);
    int L   = (sgi == 0) ? 512 : 256;
    int t = threadIdx.x;
    const float* p = x + ((long)b * SEQ + off) * HID + t;
    float s = 0.f;
    for (int i = 0; i < L; i++) s += p[(long)i * HID];
    mout[(long)blockIdx.x * HID + t] = s * (1.f / L);
}

// -------------------- final: relu((p-n+f) @ W + b) --------------------------
__global__ void final_k(const float* __restrict__ mean, const float* __restrict__ W,
                        const float* __restrict__ bias, float* __restrict__ out)
{
    int b = blockIdx.x, n = threadIdx.x;
    __shared__ float comb[HID];
    const float* mp = mean + (long)b * 3 * HID;
    comb[n] = mp[n] - mp[HID + n] + mp[2 * HID + n];
    __syncthreads();
    float s = bias[n];
#pragma unroll 8
    for (int k = 0; k < HID; k++) s += comb[k] * W[k * HID + n];
    out[(long)b * HID + n] = fmaxf(s, 0.f);
}

// ---------------------------------------------------------------------------
static void launch_gemm(const float* A, const float* B, const float* bias, float* C,
                        int M, int N, int K, int lda, int ldb, int ldc,
                        long sAb, long sAh, long sBb, long sBh, long sCb, long sCh,
                        int nheads, int batches, float alpha, int transB, int relu)
{
    dim3 grid((N + BN - 1) / BN, M / BM, batches);
    if (transB)
        gemm_tc<1><<<grid, 256>>>(A, B, bias, C, M, N, K, lda, ldb, ldc,
                                  sAb, sAh, sBb, sBh, sCb, sCh, nheads, alpha, relu);
    else
        gemm_tc<0><<<grid, 256>>>(A, B, bias, C, M, N, K, lda, ldb, ldc,
                                  sAb, sAh, sBb, sBh, sCb, sCh, nheads, alpha, relu);
}

extern "C" void kernel_launch(void* const* d_in, const int* in_sizes, int n_in,
                              void* d_out, int out_size)
{
    const int*   hyper = (const int*)  d_in[0];
    const float* HT    = (const float*)d_in[1];
    const float* emb   = (const float*)d_in[2];
    const float* Wg1   = (const float*)d_in[3];
    const float* bg1   = (const float*)d_in[4];
    const float* Wg2   = (const float*)d_in[5];
    const float* bg2   = (const float*)d_in[6];
    const float* Wqkv  = (const float*)d_in[7];
    const float* bqkv  = (const float*)d_in[8];
    const float* Wo    = (const float*)d_in[9];
    const float* bo    = (const float*)d_in[10];
    const float* ln1g  = (const float*)d_in[11];
    const float* ln1b  = (const float*)d_in[12];
    const float* Wff1  = (const float*)d_in[13];
    const float* bff1  = (const float*)d_in[14];
    const float* Wff2  = (const float*)d_in[15];
    const float* bff2  = (const float*)d_in[16];
    const float* ln2g  = (const float*)d_in[17];
    const float* ln2b  = (const float*)d_in[18];
    const float* fc1W  = (const float*)d_in[19];
    const float* fc1b  = (const float*)d_in[20];

    float *h0, *t, *x, *x1, *qkv, *sc, *ctx, *ff, *mean;
    cudaGetSymbolAddress((void**)&h0,   g_h0);
    cudaGetSymbolAddress((void**)&t,    g_t);
    cudaGetSymbolAddress((void**)&x,    g_x);
    cudaGetSymbolAddress((void**)&x1,   g_x1);
    cudaGetSymbolAddress((void**)&qkv,  g_qkv);
    cudaGetSymbolAddress((void**)&sc,   g_sc);
    cudaGetSymbolAddress((void**)&ctx,  g_ctx);
    cudaGetSymbolAddress((void**)&ff,   g_ff);
    cudaGetSymbolAddress((void**)&mean, g_mean);

    // 1. embedding gather
    gather_k<<<TOKENS, 64>>>(hyper, emb, h0);

    // 2. t = h0 @ Wg1
    launch_gemm(h0, Wg1, nullptr, t, TOKENS, HID, HID, HID, HID, HID,
                0, 0, 0, 0, 0, 0, 1, 1, 1.f, 0, 0);

    // 3. x = batched HT @ t + bg1
    launch_gemm(HT, t, bg1, x, SEQ, HID, SEQ, SEQ, HID, HID,
                (long)SEQ * SEQ, 0, (long)SEQ * HID, 0, (long)SEQ * HID, 0,
                1, NB, 1.f, 0, 0);

    // 4. t = x @ Wg2
    launch_gemm(x, Wg2, nullptr, t, TOKENS, HID, HID, HID, HID, HID,
                0, 0, 0, 0, 0, 0, 1, 1, 1.f, 0, 0);

    // 5. x = batched HT @ t + bg2
    launch_gemm(HT, t, bg2, x, SEQ, HID, SEQ, SEQ, HID, HID,
                (long)SEQ * SEQ, 0, (long)SEQ * HID, 0, (long)SEQ * HID, 0,
                1, NB, 1.f, 0, 0);

    // 6. qkv = x @ Wqkv + bqkv
    launch_gemm(x, Wqkv, bqkv, qkv, TOKENS, 3 * HID, HID, HID, 3 * HID, 3 * HID,
                0, 0, 0, 0, 0, 0, 1, 1, 1.f, 0, 0);

    // 7-9. segmented attention
    const int  segoff[3] = {0, 512, 768};
    const int  seglen[3] = {512, 256, 256};
    const long scoff[3]  = {SC0, SC1, SC2};
    const float scale = 0.125f;  // 1/sqrt(64)

    for (int s = 0; s < 3; s++) {
        int off = segoff[s], L = seglen[s];
        // scores = (Q @ K^T) * scale      [z = b*4 + head]
        launch_gemm(qkv + (long)off * 3 * HID + 0,
                    qkv + (long)off * 3 * HID + HID,
                    nullptr, sc + scoff[s],
                    L, L, DH, 3 * HID, 3 * HID, L,
                    (long)SEQ * 3 * HID, DH,
                    (long)SEQ * 3 * HID, DH,
                    (long)NHEADS * L * L, (long)L * L,
                    NHEADS, NB * NHEADS, scale, /*transB*/1, 0);
        softmax_k<<<NB * NHEADS * L, 256>>>(sc + scoff[s], L);
        // ctx = attn @ V, written into (B,S,H) layout at head column offset
        launch_gemm(sc + scoff[s],
                    qkv + (long)off * 3 * HID + 2 * HID,
                    nullptr, ctx + (long)off * HID,
                    L, DH, L, L, 3 * HID, HID,
                    (long)NHEADS * L * L, (long)L * L,
                    (long)SEQ * 3 * HID, DH,
                    (long)SEQ * HID, DH,
                    NHEADS, NB * NHEADS, 1.f, 0, 0);
    }

    // 10. t = ctx @ Wo + bo
    launch_gemm(ctx, Wo, bo, t, TOKENS, HID, HID, HID, HID, HID,
                0, 0, 0, 0, 0, 0, 1, 1, 1.f, 0, 0);

    // 11. x1 = LN1(x + t)
    add_ln_k<<<TOKENS, 256>>>(x, t, ln1g, ln1b, x1);

    // 12. ff = relu(x1 @ Wff1 + bff1)
    launch_gemm(x1, Wff1, bff1, ff, TOKENS, FF, HID, HID, FF, FF,
                0, 0, 0, 0, 0, 0, 1, 1, 1.f, 0, 2);

    // 13. t = ff @ Wff2 + bff2
    launch_gemm(ff, Wff2, bff2, t, TOKENS, HID, FF, FF, HID, HID,
                0, 0, 0, 0, 0, 0, 1, 1, 1.f, 0, 0);

    // 14. x = LN2(x1 + t)
    add_ln_k<<<TOKENS, 256>>>(x1, t, ln2g, ln2b, x);

    // 15. per-segment means
    mean_k<<<NB * 3, 256>>>(x, mean);

    // 16. out = relu((p - n + f) @ fc1W + fc1b)
    final_k<<<NB, 256>>>(mean, fc1W, fc1b, (float*)d_out);
}

// round 3
// speedup vs baseline: 2.3313x; 1.2409x over previous
#include <cuda_runtime.h>
#include <cuda_bf16.h>
#include <mma.h>

using namespace nvcuda;

// ---------------------------------------------------------------------------
// GraphEncoder: tf32 tensor-core GEMM + fused flash attention.
// Shapes: B=16, S=1024 (segments 512/256/256), H=256, heads=4 (Dh=64), F=400.
// ---------------------------------------------------------------------------

#define NB 16
#define SEQ 1024
#define HID 256
#define NHEADS 4
#define DH 64
#define FF 400
#define TOKENS (NB * SEQ)   // 16384

// -------------------- scratch (device globals; no allocation) --------------
__device__ float g_h0[TOKENS * HID];
__device__ float g_t[TOKENS * HID];
__device__ float g_x[TOKENS * HID];
__device__ float g_x1[TOKENS * HID];
__device__ float g_qkv[TOKENS * 3 * HID];
__device__ float g_ctx[TOKENS * HID];
__device__ float g_ff[TOKENS * FF];
__device__ float g_mean[NB * 3 * HID];

// -------------------- tf32 tensor-core GEMM --------------------------------
#define BM 128
#define BN 64
#define BK 16
#define APAD 20
#define BPADN 68
#define BPADT 20
#define EPI_LD 36
#define SMEM_FLOATS 9216

__device__ __forceinline__ unsigned sptr(const void* p) {
    return (unsigned)__cvta_generic_to_shared(p);
}
#define CPA16(dst, src) asm volatile("cp.async.ca.shared.global [%0], [%1], 16;" :: "r"(dst), "l"(src))
#define CPA_COMMIT()    asm volatile("cp.async.commit_group;")
#define CPA_WAIT0()     asm volatile("cp.async.wait_group 0;")

template<int TRANSB>
__global__ void __launch_bounds__(256) gemm_tc(
    const float* __restrict__ A, const float* __restrict__ Bm,
    const float* __restrict__ bias, float* __restrict__ C,
    int M, int N, int K, int lda, int ldb, int ldc,
    long sAb, long sAh, long sBb, long sBh, long sCb, long sCh,
    int nheads, float alpha, int relu)
{
    __shared__ float smem[SMEM_FLOATS];

    const int z  = blockIdx.z;
    const int bb = z / nheads, hh = z % nheads;
    A  += (long)bb * sAb + (long)hh * sAh;
    Bm += (long)bb * sBb + (long)hh * sBh;
    C  += (long)bb * sCb + (long)hh * sCh;

    const int tid = threadIdx.x;
    const int w = tid >> 5, lane = tid & 31;
    const int wm = w & 3, wn = w >> 2;
    const int rowTile = blockIdx.y * BM;
    const int colTile = blockIdx.x * BN;

    wmma::fragment<wmma::accumulator, 16, 16, 8, float> acc[2][2];
#pragma unroll
    for (int i = 0; i < 2; i++)
#pragma unroll
        for (int j = 0; j < 2; j++) wmma::fill_fragment(acc[i][j], 0.f);

    const int nk = K / BK;

    auto loadA = [&](int kt, int buf) {
        const float* Ag = A + (long)rowTile * lda + kt * BK;
        float* s = smem + buf * 2560;
#pragma unroll
        for (int i = 0; i < 2; i++) {
            int idx = tid * 2 + i;
            int r = idx >> 2, c4 = (idx & 3) * 4;
            CPA16(sptr(s + r * APAD + c4), Ag + (long)r * lda + c4);
        }
    };
    auto loadB = [&](int kt, int buf) {
        float* s = smem + 5120 + buf * 1280;
        if (!TRANSB) {
            int r = tid >> 4, c4 = (tid & 15) * 4;
            int n = colTile + c4;
            float* d = s + r * BPADN + c4;
            if (n < N) CPA16(sptr(d), Bm + (long)(kt * BK + r) * ldb + n);
            else { d[0] = 0.f; d[1] = 0.f; d[2] = 0.f; d[3] = 0.f; }
        } else {
            int r = tid >> 2, c4 = (tid & 3) * 4;
            int n = colTile + r;
            float* d = s + r * BPADT + c4;
            if (n < N) CPA16(sptr(d), Bm + (long)n * ldb + kt * BK + c4);
            else { d[0] = 0.f; d[1] = 0.f; d[2] = 0.f; d[3] = 0.f; }
        }
    };

    loadA(0, 0); loadB(0, 0); CPA_COMMIT();

    int buf = 0;
    for (int kt = 0; kt < nk; kt++) {
        CPA_WAIT0();
        __syncthreads();
        if (kt + 1 < nk) { loadA(kt + 1, buf ^ 1); loadB(kt + 1, buf ^ 1); CPA_COMMIT(); }

        const float* As_ = smem + buf * 2560;
        const float* Bs_ = smem + 5120 + buf * 1280;

#pragma unroll
        for (int ks = 0; ks < 2; ks++) {
            wmma::fragment<wmma::matrix_a, 16, 16, 8, wmma::precision::tf32, wmma::row_major> af[2];
#pragma unroll
            for (int mi = 0; mi < 2; mi++)
                wmma::load_matrix_sync(af[mi], As_ + (wm * 32 + mi * 16) * APAD + ks * 8, APAD);
            if (!TRANSB) {
                wmma::fragment<wmma::matrix_b, 16, 16, 8, wmma::precision::tf32, wmma::row_major> bf[2];
#pragma unroll
                for (int ni = 0; ni < 2; ni++)
                    wmma::load_matrix_sync(bf[ni], Bs_ + (ks * 8) * BPADN + wn * 32 + ni * 16, BPADN);
#pragma unroll
                for (int mi = 0; mi < 2; mi++)
#pragma unroll
                    for (int ni = 0; ni < 2; ni++)
                        wmma::mma_sync(acc[mi][ni], af[mi], bf[ni], acc[mi][ni]);
            } else {
                wmma::fragment<wmma::matrix_b, 16, 16, 8, wmma::precision::tf32, wmma::col_major> bf[2];
#pragma unroll
                for (int ni = 0; ni < 2; ni++)
                    wmma::load_matrix_sync(bf[ni], Bs_ + (wn * 32 + ni * 16) * BPADT + ks * 8, BPADT);
#pragma unroll
                for (int mi = 0; mi < 2; mi++)
#pragma unroll
                    for (int ni = 0; ni < 2; ni++)
                        wmma::mma_sync(acc[mi][ni], af[mi], bf[ni], acc[mi][ni]);
            }
        }
        __syncthreads();
        buf ^= 1;
    }

    float* ep = smem + w * 1152;
#pragma unroll
    for (int mi = 0; mi < 2; mi++)
#pragma unroll
        for (int ni = 0; ni < 2; ni++)
            wmma::store_matrix_sync(ep + (mi * 16) * EPI_LD + ni * 16, acc[mi][ni],
                                    EPI_LD, wmma::mem_row_major);
    __syncwarp();

    const int m0 = rowTile + wm * 32;
    const int n  = colTile + wn * 32 + lane;
    if (n < N) {
        float bv = bias ? bias[n] : 0.f;
#pragma unroll 4
        for (int r = 0; r < 32; r++) {
            float v = ep[r * EPI_LD + lane] * alpha + bv;
            if (relu) v = fmaxf(v, 0.f);
            C[(long)(m0 + r) * ldc + n] = v;
        }
    }
}

// -------------------- fused flash attention --------------------------------
// Per CTA: 128 query rows of one (batch, head, segment). KV tiles of 128.
// qkv row layout per token: [q(4x64) | k(4x64) | v(4x64)] = 768 floats.
#define QLD 68
#define SLD 132
// smem float offsets
#define FS_Q 0
#define FS_K 8704
#define FS_V 17408
#define FS_O 26112
#define FS_S 34816
#define FS_AL 51712
#define FS_M 51840
#define FS_L 51968
#define FLASH_SMEM_BYTES ((51968 + 128) * 4)

__global__ void __launch_bounds__(256) flash_k(
    const float* __restrict__ qkv, float* __restrict__ ctx, int segOff, int L)
{
    extern __shared__ float sm[];
    float* sQ = sm + FS_Q;
    float* sK = sm + FS_K;
    float* sV = sm + FS_V;
    float* sO = sm + FS_O;
    float* sS = sm + FS_S;
    float* al = sm + FS_AL;
    float* mrow = sm + FS_M;
    float* lrow = sm + FS_L;

    const int bh = blockIdx.y;
    const int b = bh >> 2, h = bh & 3;
    const int qt = blockIdx.x;
    const int tid = threadIdx.x;
    const int w = tid >> 5;
    const int wm = w & 3, wn = w >> 2;

    const float* base = qkv + ((long)b * SEQ + segOff) * 768 + h * 64;
    const float* Qg = base + (long)qt * 128 * 768;

    // load Q tile, zero O
#pragma unroll
    for (int i = 0; i < 8; i++) {
        int idx = tid + i * 256;          // 2048 float4s
        int r = idx >> 4, c4 = (idx & 15) * 4;
        *(float4*)(sQ + r * QLD + c4) = *(const float4*)(Qg + (long)r * 768 + c4);
        *(float4*)(sO + r * QLD + c4) = make_float4(0.f, 0.f, 0.f, 0.f);
    }
    if (tid < 128) { mrow[tid] = -1e30f; lrow[tid] = 0.f; }
    __syncthreads();

    const int nt = L >> 7;
    for (int t = 0; t < nt; t++) {
        const float* Kg = base + 256 + (long)t * 128 * 768;
        const float* Vg = base + 512 + (long)t * 128 * 768;
#pragma unroll
        for (int i = 0; i < 8; i++) {
            int idx = tid + i * 256;
            int r = idx >> 4, c4 = (idx & 15) * 4;
            *(float4*)(sK + r * QLD + c4) = *(const float4*)(Kg + (long)r * 768 + c4);
            *(float4*)(sV + r * QLD + c4) = *(const float4*)(Vg + (long)r * 768 + c4);
        }
        __syncthreads();

        // ---- S = Q @ K^T  (warp: rows wm*32+.., cols wn*64+..) ----
        {
            wmma::fragment<wmma::accumulator, 16, 16, 8, float> sacc[2][4];
#pragma unroll
            for (int mi = 0; mi < 2; mi++)
#pragma unroll
                for (int ni = 0; ni < 4; ni++) wmma::fill_fragment(sacc[mi][ni], 0.f);
#pragma unroll
            for (int k = 0; k < DH; k += 8) {
                wmma::fragment<wmma::matrix_a, 16, 16, 8, wmma::precision::tf32, wmma::row_major> af[2];
#pragma unroll
                for (int mi = 0; mi < 2; mi++)
                    wmma::load_matrix_sync(af[mi], sQ + (wm * 32 + mi * 16) * QLD + k, QLD);
                wmma::fragment<wmma::matrix_b, 16, 16, 8, wmma::precision::tf32, wmma::col_major> bf[4];
#pragma unroll
                for (int ni = 0; ni < 4; ni++)
                    wmma::load_matrix_sync(bf[ni], sK + (wn * 64 + ni * 16) * QLD + k, QLD);
#pragma unroll
                for (int mi = 0; mi < 2; mi++)
#pragma unroll
                    for (int ni = 0; ni < 4; ni++)
                        wmma::mma_sync(sacc[mi][ni], af[mi], bf[ni], sacc[mi][ni]);
            }
#pragma unroll
            for (int mi = 0; mi < 2; mi++)
#pragma unroll
                for (int ni = 0; ni < 4; ni++)
                    wmma::store_matrix_sync(sS + (wm * 32 + mi * 16) * SLD + wn * 64 + ni * 16,
                                            sacc[mi][ni], SLD, wmma::mem_row_major);
        }
        __syncthreads();

        // ---- online softmax on S (2 threads per row) ----
        {
            const int r = tid >> 1, hf = tid & 1;
            float* row = sS + r * SLD + hf * 64;
            float mx = -1e30f;
#pragma unroll 8
            for (int c = 0; c < 64; c++) mx = fmaxf(mx, row[c]);
            mx = fmaxf(mx, __shfl_xor_sync(0xffffffffu, mx, 1));
            mx *= 0.125f;
            float m_old = mrow[r];
            float m_new = fmaxf(m_old, mx);
            float a = __expf(m_old - m_new);
            float sum = 0.f;
#pragma unroll 8
            for (int c = 0; c < 64; c++) {
                float p = __expf(row[c] * 0.125f - m_new);
                row[c] = p;
                sum += p;
            }
            sum += __shfl_xor_sync(0xffffffffu, sum, 1);
            if (hf == 0) {
                mrow[r] = m_new;
                lrow[r] = lrow[r] * a + sum;
                al[r] = a;
            }
        }
        __syncthreads();

        // ---- PV = P @ V  (warp: rows wm*32+.., cols wn*32+..) ----
        {
            wmma::fragment<wmma::accumulator, 16, 16, 8, float> oacc[2][2];
#pragma unroll
            for (int mi = 0; mi < 2; mi++)
#pragma unroll
                for (int ni = 0; ni < 2; ni++) wmma::fill_fragment(oacc[mi][ni], 0.f);
#pragma unroll
            for (int k = 0; k < 128; k += 8) {
                wmma::fragment<wmma::matrix_a, 16, 16, 8, wmma::precision::tf32, wmma::row_major> af[2];
#pragma unroll
                for (int mi = 0; mi < 2; mi++)
                    wmma::load_matrix_sync(af[mi], sS + (wm * 32 + mi * 16) * SLD + k, SLD);
                wmma::fragment<wmma::matrix_b, 16, 16, 8, wmma::precision::tf32, wmma::row_major> bf[2];
#pragma unroll
                for (int ni = 0; ni < 2; ni++)
                    wmma::load_matrix_sync(bf[ni], sV + k * QLD + wn * 32 + ni * 16, QLD);
#pragma unroll
                for (int mi = 0; mi < 2; mi++)
#pragma unroll
                    for (int ni = 0; ni < 2; ni++)
                        wmma::mma_sync(oacc[mi][ni], af[mi], bf[ni], oacc[mi][ni]);
            }
            __syncthreads();   // all warps done reading sS
#pragma unroll
            for (int mi = 0; mi < 2; mi++)
#pragma unroll
                for (int ni = 0; ni < 2; ni++)
                    wmma::store_matrix_sync(sS + (wm * 32 + mi * 16) * SLD + wn * 32 + ni * 16,
                                            oacc[mi][ni], SLD, wmma::mem_row_major);
        }
        __syncthreads();

        // ---- O = O * alpha + PV ----
        {
            const int r = tid >> 1, hf = tid & 1;
            const float a = al[r];
            float* orow = sO + r * QLD + hf * 32;
            const float* prow = sS + r * SLD + hf * 32;
#pragma unroll 8
            for (int c = 0; c < 32; c++) orow[c] = orow[c] * a + prow[c];
        }
        __syncthreads();
    }

    // ---- write ctx = O / l ----
    float* out = ctx + ((long)b * SEQ + segOff + (long)qt * 128) * HID + h * 64;
    {
        const int r = tid >> 1, hf = tid & 1;
        const float inv = 1.f / lrow[r];
#pragma unroll
        for (int c4 = 0; c4 < 32; c4 += 4) {
            int c = hf * 32 + c4;
            float4 v = *(float4*)(sO + r * QLD + c);
            v.x *= inv; v.y *= inv; v.z *= inv; v.w *= inv;
            *(float4*)(out + (long)r * HID + c) = v;
        }
    }
}

// -------------------- embedding gather -------------------------------------
__global__ void gather_k(const int* __restrict__ idx,
                         const float* __restrict__ tab,
                         float* __restrict__ out)
{
    long tok = blockIdx.x;
    int id = idx[tok];
    const float4* src = (const float4*)(tab + (long)id * HID);
    float4* dst = (float4*)(out + tok * HID);
    dst[threadIdx.x] = src[threadIdx.x];
}

// -------------------- residual add + layernorm ------------------------------
__global__ void add_ln_k(const float* __restrict__ x, const float* __restrict__ y,
                         const float* __restrict__ g, const float* __restrict__ b,
                         float* __restrict__ out)
{
    long row = blockIdx.x;
    int t = threadIdx.x;  // 256 == HID
    __shared__ float red[256];

    float v = x[row * HID + t] + y[row * HID + t];
    red[t] = v; __syncthreads();
    for (int s = 128; s > 0; s >>= 1) { if (t < s) red[t] += red[t + s]; __syncthreads(); }
    float mu = red[0] * (1.f / HID);
    __syncthreads();
    float d = v - mu;
    red[t] = d * d; __syncthreads();
    for (int s = 128; s > 0; s >>= 1) { if (t < s) red[t] += red[t + s]; __syncthreads(); }
    float var = red[0] * (1.f / HID);
    out[row * HID + t] = d * rsqrtf(var + 1e-5f) * g[t] + b[t];
}

// -------------------- per-segment mean --------------------------------------
__global__ void mean_k(const float* __restrict__ x, float* __restrict__ mout)
{
    int b = blockIdx.x / 3, sgi = blockIdx.x % 3;
    int off = (sgi == 0) ? 0 : (sgi == 1 ? 512 : 768);
    int L   = (sgi == 0) ? 512 : 256;
    int t = threadIdx.x;
    const float* p = x + ((long)b * SEQ + off) * HID + t;
    float s = 0.f;
    for (int i = 0; i < L; i++) s += p[(long)i * HID];
    mout[(long)blockIdx.x * HID + t] = s * (1.f / L);
}

// -------------------- final: relu((p-n+f) @ W + b) --------------------------
__global__ void final_k(const float* __restrict__ mean, const float* __restrict__ W,
                        const float* __restrict__ bias, float* __restrict__ out)
{
    int b = blockIdx.x, n = threadIdx.x;
    __shared__ float comb[HID];
    const float* mp = mean + (long)b * 3 * HID;
    comb[n] = mp[n] - mp[HID + n] + mp[2 * HID + n];
    __syncthreads();
    float s = bias[n];
#pragma unroll 8
    for (int k = 0; k < HID; k++) s += comb[k] * W[k * HID + n];
    out[(long)b * HID + n] = fmaxf(s, 0.f);
}

// ---------------------------------------------------------------------------
static void launch_gemm(const float* A, const float* B, const float* bias, float* C,
                        int M, int N, int K, int lda, int ldb, int ldc,
                        long sAb, long sAh, long sBb, long sBh, long sCb, long sCh,
                        int nheads, int batches, float alpha, int transB, int relu)
{
    dim3 grid((N + BN - 1) / BN, M / BM, batches);
    if (transB)
        gemm_tc<1><<<grid, 256>>>(A, B, bias, C, M, N, K, lda, ldb, ldc,
                                  sAb, sAh, sBb, sBh, sCb, sCh, nheads, alpha, relu);
    else
        gemm_tc<0><<<grid, 256>>>(A, B, bias, C, M, N, K, lda, ldb, ldc,
                                  sAb, sAh, sBb, sBh, sCb, sCh, nheads, alpha, relu);
}

extern "C" void kernel_launch(void* const* d_in, const int* in_sizes, int n_in,
                              void* d_out, int out_size)
{
    const int*   hyper = (const int*)  d_in[0];
    const float* HT    = (const float*)d_in[1];
    const float* emb   = (const float*)d_in[2];
    const float* Wg1   = (const float*)d_in[3];
    const float* bg1   = (const float*)d_in[4];
    const float* Wg2   = (const float*)d_in[5];
    const float* bg2   = (const float*)d_in[6];
    const float* Wqkv  = (const float*)d_in[7];
    const float* bqkv  = (const float*)d_in[8];
    const float* Wo    = (const float*)d_in[9];
    const float* bo    = (const float*)d_in[10];
    const float* ln1g  = (const float*)d_in[11];
    const float* ln1b  = (const float*)d_in[12];
    const float* Wff1  = (const float*)d_in[13];
    const float* bff1  = (const float*)d_in[14];
    const float* Wff2  = (const float*)d_in[15];
    const float* bff2  = (const float*)d_in[16];
    const float* ln2g  = (const float*)d_in[17];
    const float* ln2b  = (const float*)d_in[18];
    const float* fc1W  = (const float*)d_in[19];
    const float* fc1b  = (const float*)d_in[20];

    float *h0, *t, *x, *x1, *qkv, *ctx, *ff, *mean;
    cudaGetSymbolAddress((void**)&h0,   g_h0);
    cudaGetSymbolAddress((void**)&t,    g_t);
    cudaGetSymbolAddress((void**)&x,    g_x);
    cudaGetSymbolAddress((void**)&x1,   g_x1);
    cudaGetSymbolAddress((void**)&qkv,  g_qkv);
    cudaGetSymbolAddress((void**)&ctx,  g_ctx);
    cudaGetSymbolAddress((void**)&ff,   g_ff);
    cudaGetSymbolAddress((void**)&mean, g_mean);

    static bool attr_done = false;
    if (!attr_done) {
        cudaFuncSetAttribute(flash_k, cudaFuncAttributeMaxDynamicSharedMemorySize,
                             FLASH_SMEM_BYTES);
        attr_done = true;
    }

    // 1. embedding gather
    gather_k<<<TOKENS, 64>>>(hyper, emb, h0);

    // 2. t = h0 @ Wg1
    launch_gemm(h0, Wg1, nullptr, t, TOKENS, HID, HID, HID, HID, HID,
                0, 0, 0, 0, 0, 0, 1, 1, 1.f, 0, 0);

    // 3. x = batched HT @ t + bg1
    launch_gemm(HT, t, bg1, x, SEQ, HID, SEQ, SEQ, HID, HID,
                (long)SEQ * SEQ, 0, (long)SEQ * HID, 0, (long)SEQ * HID, 0,
                1, NB, 1.f, 0, 0);

    // 4. t = x @ Wg2
    launch_gemm(x, Wg2, nullptr, t, TOKENS, HID, HID, HID, HID, HID,
                0, 0, 0, 0, 0, 0, 1, 1, 1.f, 0, 0);

    // 5. x = batched HT @ t + bg2
    launch_gemm(HT, t, bg2, x, SEQ, HID, SEQ, SEQ, HID, HID,
                (long)SEQ * SEQ, 0, (long)SEQ * HID, 0, (long)SEQ * HID, 0,
                1, NB, 1.f, 0, 0);

    // 6. qkv = x @ Wqkv + bqkv
    launch_gemm(x, Wqkv, bqkv, qkv, TOKENS, 3 * HID, HID, HID, 3 * HID, 3 * HID,
                0, 0, 0, 0, 0, 0, 1, 1, 1.f, 0, 0);

    // 7. fused flash attention per segment
    flash_k<<<dim3(4, NB * NHEADS), 256, FLASH_SMEM_BYTES>>>(qkv, ctx, 0, 512);
    flash_k<<<dim3(2, NB * NHEADS), 256, FLASH_SMEM_BYTES>>>(qkv, ctx, 512, 256);
    flash_k<<<dim3(2, NB * NHEADS), 256, FLASH_SMEM_BYTES>>>(qkv, ctx, 768, 256);

    // 8. t = ctx @ Wo + bo
    launch_gemm(ctx, Wo, bo, t, TOKENS, HID, HID, HID, HID, HID,
                0, 0, 0, 0, 0, 0, 1, 1, 1.f, 0, 0);

    // 9. x1 = LN1(x + t)
    add_ln_k<<<TOKENS, 256>>>(x, t, ln1g, ln1b, x1);

    // 10. ff = relu(x1 @ Wff1 + bff1)
    launch_gemm(x1, Wff1, bff1, ff, TOKENS, FF, HID, HID, FF, FF,
                0, 0, 0, 0, 0, 0, 1, 1, 1.f, 0, 2);

    // 11. t = ff @ Wff2 + bff2
    launch_gemm(ff, Wff2, bff2, t, TOKENS, HID, FF, FF, HID, HID,
                0, 0, 0, 0, 0, 0, 1, 1, 1.f, 0, 0);

    // 12. x = LN2(x1 + t)
    add_ln_k<<<TOKENS, 256>>>(x1, t, ln2g, ln2b, x);

    // 13. per-segment means
    mean_k<<<NB * 3, 256>>>(x, mean);

    // 14. out = relu((p - n + f) @ fc1W + fc1b)
    final_k<<<NB, 256>>>(mean, fc1W, fc1b, (float*)d_out);
}

// round 4
// speedup vs baseline: 2.3729x; 1.0178x over previous
#include <cuda_runtime.h>
#include <cuda_bf16.h>
#include <mma.h>

using namespace nvcuda;

// ---------------------------------------------------------------------------
// GraphEncoder: tf32 tensor-core GEMM (128x128x16, 3-stage) + flash attention.
// Shapes: B=16, S=1024 (segments 512/256/256), H=256, heads=4 (Dh=64), F=400.
// ---------------------------------------------------------------------------

#define NB 16
#define SEQ 1024
#define HID 256
#define NHEADS 4
#define DH 64
#define FFP 512            // padded FF width (400 -> 512)
#define TOKENS (NB * SEQ)  // 16384

// -------------------- scratch (device globals; no allocation) --------------
__device__ float g_h0[TOKENS * HID];
__device__ float g_t[TOKENS * HID];
__device__ float g_x[TOKENS * HID];
__device__ float g_x1[TOKENS * HID];
__device__ float g_qkv[TOKENS * 3 * HID];
__device__ float g_ctx[TOKENS * HID];
__device__ float g_ff[TOKENS * FFP];
__device__ float g_mean[NB * 3 * HID];
__device__ float g_w1p[HID * FFP];     // padded Wff1 (256 x 512)
__device__ float g_b1p[FFP];           // padded bff1
__device__ float g_w2p[FFP * HID];     // padded Wff2 (512 x 256)

// -------------------- tf32 tensor-core GEMM --------------------------------
// C[m,n] = sum_k A[m,k] * B[k,n] + bias[n] (relu?)   — exact tiles only:
// M % 128 == 0, N % 128 == 0, K % 16 == 0 guaranteed by call sites.
#define BM 128
#define BN 128
#define BK 16
#define APAD 20
#define BPAD 132
#define AS_STAGE (BM * APAD)                    // 2560 floats
#define BS_STAGE (BK * BPAD)                    // 2112 floats
#define STAGES 3
#define BIAS_OFF (STAGES * (AS_STAGE + BS_STAGE))   // 14016
#define GEMM_SMEM_BYTES ((BIAS_OFF + 16 * BPAD) * 4)  // ~64.5 KB

__device__ __forceinline__ unsigned sptr(const void* p) {
    return (unsigned)__cvta_generic_to_shared(p);
}
#define CPA16(dst, src) asm volatile("cp.async.ca.shared.global [%0], [%1], 16;" :: "r"(dst), "l"(src))
#define CPA_COMMIT()    asm volatile("cp.async.commit_group;")
#define CPA_WAIT1()     asm volatile("cp.async.wait_group 1;")

__global__ void __launch_bounds__(256, 1) gemm_tc(
    const float* __restrict__ A, const float* __restrict__ Bm,
    const float* __restrict__ bias, float* __restrict__ C,
    int K, int lda, int ldb, int ldc,
    long sAb, long sBb, long sCb, int relu)
{
    extern __shared__ float sm[];

    const int z = blockIdx.z;
    A  += (long)z * sAb;
    Bm += (long)z * sBb;
    C  += (long)z * sCb;

    const int tid = threadIdx.x;
    const int w = tid >> 5;
    const int wm = w & 1, wn = w >> 1;           // 2 x 4 warp grid, 64x32 tiles
    const int rowTile = blockIdx.y * BM;
    const int colTile = blockIdx.x * BN;

    // ---- loaders ----
    auto loadA = [&](int kt, int s) {
        const float* Ag = A + (long)rowTile * lda + kt * BK;
        float* sa = sm + s * AS_STAGE;
#pragma unroll
        for (int i = 0; i < 2; i++) {
            int idx = tid + i * 256;             // 512 float4s: 128 rows x 4
            int r = idx >> 2, c4 = (idx & 3) * 4;
            CPA16(sptr(sa + r * APAD + c4), Ag + (long)r * lda + c4);
        }
    };
    auto loadB = [&](int kt, int s) {
        const float* Bg = Bm + (long)(kt * BK) * ldb + colTile;
        float* sb = sm + STAGES * AS_STAGE + s * BS_STAGE;
#pragma unroll
        for (int i = 0; i < 2; i++) {
            int idx = tid + i * 256;             // 512 float4s: 16 rows x 32
            int r = idx >> 5, c4 = (idx & 31) * 4;
            CPA16(sptr(sb + r * BPAD + c4), Bg + (long)r * ldb + c4);
        }
    };

    // bias strip (16 identical rows) for accumulator init
    float* biasm = sm + BIAS_OFF;
    if (bias) {
        for (int i = tid; i < 16 * 128; i += 256) {
            int r = i >> 7, c = i & 127;
            biasm[r * BPAD + c] = bias[colTile + c];
        }
    }

    loadA(0, 0); loadB(0, 0); CPA_COMMIT();
    loadA(1, 1); loadB(1, 1); CPA_COMMIT();
    __syncthreads();   // biasm visible

    wmma::fragment<wmma::accumulator, 16, 16, 8, float> acc[4][2];
    if (bias) {
#pragma unroll
        for (int ni = 0; ni < 2; ni++) {
            wmma::load_matrix_sync(acc[0][ni], biasm + wn * 32 + ni * 16, BPAD,
                                   wmma::mem_row_major);
#pragma unroll
            for (int mi = 1; mi < 4; mi++) acc[mi][ni] = acc[0][ni];
        }
    } else {
#pragma unroll
        for (int mi = 0; mi < 4; mi++)
#pragma unroll
            for (int ni = 0; ni < 2; ni++) wmma::fill_fragment(acc[mi][ni], 0.f);
    }

    const int nk = K / BK;
    for (int kt = 0; kt < nk; kt++) {
        CPA_WAIT1();
        __syncthreads();
        if (kt + 2 < nk) { int s = (kt + 2) % STAGES; loadA(kt + 2, s); loadB(kt + 2, s); CPA_COMMIT(); }

        const float* sa = sm + (kt % STAGES) * AS_STAGE;
        const float* sb = sm + STAGES * AS_STAGE + (kt % STAGES) * BS_STAGE;

#pragma unroll
        for (int ks = 0; ks < 2; ks++) {
            wmma::fragment<wmma::matrix_a, 16, 16, 8, wmma::precision::tf32, wmma::row_major> af[4];
#pragma unroll
            for (int mi = 0; mi < 4; mi++)
                wmma::load_matrix_sync(af[mi], sa + (wm * 64 + mi * 16) * APAD + ks * 8, APAD);
            wmma::fragment<wmma::matrix_b, 16, 16, 8, wmma::precision::tf32, wmma::row_major> bf[2];
#pragma unroll
            for (int ni = 0; ni < 2; ni++)
                wmma::load_matrix_sync(bf[ni], sb + (ks * 8) * BPAD + wn * 32 + ni * 16, BPAD);
#pragma unroll
            for (int mi = 0; mi < 4; mi++)
#pragma unroll
                for (int ni = 0; ni < 2; ni++)
                    wmma::mma_sync(acc[mi][ni], af[mi], bf[ni], acc[mi][ni]);
        }
    }

    // ---- direct epilogue ----
#pragma unroll
    for (int mi = 0; mi < 4; mi++)
#pragma unroll
        for (int ni = 0; ni < 2; ni++) {
            if (relu)
#pragma unroll
                for (int e = 0; e < acc[mi][ni].num_elements; e++)
                    acc[mi][ni].x[e] = fmaxf(acc[mi][ni].x[e], 0.f);
            wmma::store_matrix_sync(
                C + (long)(rowTile + wm * 64 + mi * 16) * ldc + colTile + wn * 32 + ni * 16,
                acc[mi][ni], ldc, wmma::mem_row_major);
        }
}

// -------------------- fused flash attention --------------------------------
#define QLD 68
#define SLD 132
#define FS_Q 0
#define FS_K 8704
#define FS_V 17408
#define FS_O 26112
#define FS_S 34816
#define FS_AL 51712
#define FS_M 51840
#define FS_L 51968
#define FLASH_SMEM_BYTES ((51968 + 128) * 4)

__global__ void __launch_bounds__(256) flash_k(
    const float* __restrict__ qkv, float* __restrict__ ctx, int segOff, int L)
{
    extern __shared__ float sm[];
    float* sQ = sm + FS_Q;
    float* sK = sm + FS_K;
    float* sV = sm + FS_V;
    float* sO = sm + FS_O;
    float* sS = sm + FS_S;
    float* al = sm + FS_AL;
    float* mrow = sm + FS_M;
    float* lrow = sm + FS_L;

    const int bh = blockIdx.y;
    const int b = bh >> 2, h = bh & 3;
    const int qt = blockIdx.x;
    const int tid = threadIdx.x;
    const int w = tid >> 5;
    const int wm = w & 3, wn = w >> 2;

    const float* base = qkv + ((long)b * SEQ + segOff) * 768 + h * 64;
    const float* Qg = base + (long)qt * 128 * 768;

#pragma unroll
    for (int i = 0; i < 8; i++) {
        int idx = tid + i * 256;
        int r = idx >> 4, c4 = (idx & 15) * 4;
        *(float4*)(sQ + r * QLD + c4) = *(const float4*)(Qg + (long)r * 768 + c4);
        *(float4*)(sO + r * QLD + c4) = make_float4(0.f, 0.f, 0.f, 0.f);
    }
    if (tid < 128) { mrow[tid] = -1e30f; lrow[tid] = 0.f; }
    __syncthreads();

    const int nt = L >> 7;
    for (int t = 0; t < nt; t++) {
        const float* Kg = base + 256 + (long)t * 128 * 768;
        const float* Vg = base + 512 + (long)t * 128 * 768;
#pragma unroll
        for (int i = 0; i < 8; i++) {
            int idx = tid + i * 256;
            int r = idx >> 4, c4 = (idx & 15) * 4;
            *(float4*)(sK + r * QLD + c4) = *(const float4*)(Kg + (long)r * 768 + c4);
            *(float4*)(sV + r * QLD + c4) = *(const float4*)(Vg + (long)r * 768 + c4);
        }
        __syncthreads();

        {
            wmma::fragment<wmma::accumulator, 16, 16, 8, float> sacc[2][4];
#pragma unroll
            for (int mi = 0; mi < 2; mi++)
#pragma unroll
                for (int ni = 0; ni < 4; ni++) wmma::fill_fragment(sacc[mi][ni], 0.f);
#pragma unroll
            for (int k = 0; k < DH; k += 8) {
                wmma::fragment<wmma::matrix_a, 16, 16, 8, wmma::precision::tf32, wmma::row_major> af[2];
#pragma unroll
                for (int mi = 0; mi < 2; mi++)
                    wmma::load_matrix_sync(af[mi], sQ + (wm * 32 + mi * 16) * QLD + k, QLD);
                wmma::fragment<wmma::matrix_b, 16, 16, 8, wmma::precision::tf32, wmma::col_major> bf[4];
#pragma unroll
                for (int ni = 0; ni < 4; ni++)
                    wmma::load_matrix_sync(bf[ni], sK + (wn * 64 + ni * 16) * QLD + k, QLD);
#pragma unroll
                for (int mi = 0; mi < 2; mi++)
#pragma unroll
                    for (int ni = 0; ni < 4; ni++)
                        wmma::mma_sync(sacc[mi][ni], af[mi], bf[ni], sacc[mi][ni]);
            }
#pragma unroll
            for (int mi = 0; mi < 2; mi++)
#pragma unroll
                for (int ni = 0; ni < 4; ni++)
                    wmma::store_matrix_sync(sS + (wm * 32 + mi * 16) * SLD + wn * 64 + ni * 16,
                                            sacc[mi][ni], SLD, wmma::mem_row_major);
        }
        __syncthreads();

        {
            const int r = tid >> 1, hf = tid & 1;
            float* row = sS + r * SLD + hf * 64;
            float mx = -1e30f;
#pragma unroll 8
            for (int c = 0; c < 64; c++) mx = fmaxf(mx, row[c]);
            mx = fmaxf(mx, __shfl_xor_sync(0xffffffffu, mx, 1));
            mx *= 0.125f;
            float m_old = mrow[r];
            float m_new = fmaxf(m_old, mx);
            float a = __expf(m_old - m_new);
            float sum = 0.f;
#pragma unroll 8
            for (int c = 0; c < 64; c++) {
                float p = __expf(row[c] * 0.125f - m_new);
                row[c] = p;
                sum += p;
            }
            sum += __shfl_xor_sync(0xffffffffu, sum, 1);
            if (hf == 0) {
                mrow[r] = m_new;
                lrow[r] = lrow[r] * a + sum;
                al[r] = a;
            }
        }
        __syncthreads();

        {
            wmma::fragment<wmma::accumulator, 16, 16, 8, float> oacc[2][2];
#pragma unroll
            for (int mi = 0; mi < 2; mi++)
#pragma unroll
                for (int ni = 0; ni < 2; ni++) wmma::fill_fragment(oacc[mi][ni], 0.f);
#pragma unroll
            for (int k = 0; k < 128; k += 8) {
                wmma::fragment<wmma::matrix_a, 16, 16, 8, wmma::precision::tf32, wmma::row_major> af[2];
#pragma unroll
                for (int mi = 0; mi < 2; mi++)
                    wmma::load_matrix_sync(af[mi], sS + (wm * 32 + mi * 16) * SLD + k, SLD);
                wmma::fragment<wmma::matrix_b, 16, 16, 8, wmma::precision::tf32, wmma::row_major> bf[2];
#pragma unroll
                for (int ni = 0; ni < 2; ni++)
                    wmma::load_matrix_sync(bf[ni], sV + k * QLD + wn * 32 + ni * 16, QLD);
#pragma unroll
                for (int mi = 0; mi < 2; mi++)
#pragma unroll
                    for (int ni = 0; ni < 2; ni++)
                        wmma::mma_sync(oacc[mi][ni], af[mi], bf[ni], oacc[mi][ni]);
            }
            __syncthreads();
#pragma unroll
            for (int mi = 0; mi < 2; mi++)
#pragma unroll
                for (int ni = 0; ni < 2; ni++)
                    wmma::store_matrix_sync(sS + (wm * 32 + mi * 16) * SLD + wn * 32 + ni * 16,
                                            oacc[mi][ni], SLD, wmma::mem_row_major);
        }
        __syncthreads();

        {
            const int r = tid >> 1, hf = tid & 1;
            const float a = al[r];
            float* orow = sO + r * QLD + hf * 32;
            const float* prow = sS + r * SLD + hf * 32;
#pragma unroll 8
            for (int c = 0; c < 32; c++) orow[c] = orow[c] * a + prow[c];
        }
        __syncthreads();
    }

    float* out = ctx + ((long)b * SEQ + segOff + (long)qt * 128) * HID + h * 64;
    {
        const int r = tid >> 1, hf = tid & 1;
        const float inv = 1.f / lrow[r];
#pragma unroll
        for (int c4 = 0; c4 < 32; c4 += 4) {
            int c = hf * 32 + c4;
            float4 v = *(float4*)(sO + r * QLD + c);
            v.x *= inv; v.y *= inv; v.z *= inv; v.w *= inv;
            *(float4*)(out + (long)r * HID + c) = v;
        }
    }
}

// -------------------- small kernels -----------------------------------------
__global__ void gather_k(const int* __restrict__ idx,
                         const float* __restrict__ tab,
                         float* __restrict__ out)
{
    long tok = blockIdx.x;
    int id = idx[tok];
    const float4* src = (const float4*)(tab + (long)id * HID);
    float4* dst = (float4*)(out + tok * HID);
    dst[threadIdx.x] = src[threadIdx.x];
}

__global__ void pad_w1_k(const float* __restrict__ w, float* __restrict__ o)
{
    int i = blockIdx.x * 256 + threadIdx.x;   // 256*512 elems
    int r = i >> 9, c = i & 511;
    o[i] = (c < 400) ? w[r * 400 + c] : 0.f;
}
__global__ void pad_b1_k(const float* __restrict__ b, float* __restrict__ o)
{
    int c = threadIdx.x + blockIdx.x * 256;
    o[c] = (c < 400) ? b[c] : 0.f;
}
__global__ void pad_w2_k(const float* __restrict__ w, float* __restrict__ o)
{
    int i = blockIdx.x * 256 + threadIdx.x;   // 512*256 elems
    int r = i >> 8, c = i & 255;
    o[i] = (r < 400) ? w[r * 256 + c] : 0.f;
}

__global__ void add_ln_k(const float* __restrict__ x, const float* __restrict__ y,
                         const float* __restrict__ g, const float* __restrict__ b,
                         float* __restrict__ out)
{
    long row = blockIdx.x;
    int t = threadIdx.x;
    __shared__ float red[256];

    float v = x[row * HID + t] + y[row * HID + t];
    red[t] = v; __syncthreads();
    for (int s = 128; s > 0; s >>= 1) { if (t < s) red[t] += red[t + s]; __syncthreads(); }
    float mu = red[0] * (1.f / HID);
    __syncthreads();
    float d = v - mu;
    red[t] = d * d; __syncthreads();
    for (int s = 128; s > 0; s >>= 1) { if (t < s) red[t] += red[t + s]; __syncthreads(); }
    float var = red[0] * (1.f / HID);
    out[row * HID + t] = d * rsqrtf(var + 1e-5f) * g[t] + b[t];
}

__global__ void mean_k(const float* __restrict__ x, float* __restrict__ mout)
{
    int b = blockIdx.x / 3, sgi = blockIdx.x % 3;
    int off = (sgi == 0) ? 0 : (sgi == 1 ? 512 : 768);
    int L   = (sgi == 0) ? 512 : 256;
    int t = threadIdx.x;
    const float* p = x + ((long)b * SEQ + off) * HID + t;
    float s = 0.f;
    for (int i = 0; i < L; i++) s += p[(long)i * HID];
    mout[(long)blockIdx.x * HID + t] = s * (1.f / L);
}

__global__ void final_k(const float* __restrict__ mean, const float* __restrict__ W,
                        const float* __restrict__ bias, float* __restrict__ out)
{
    int b = blockIdx.x, n = threadIdx.x;
    __shared__ float comb[HID];
    const float* mp = mean + (long)b * 3 * HID;
    comb[n] = mp[n] - mp[HID + n] + mp[2 * HID + n];
    __syncthreads();
    float s = bias[n];
#pragma unroll 8
    for (int k = 0; k < HID; k++) s += comb[k] * W[k * HID + n];
    out[(long)b * HID + n] = fmaxf(s, 0.f);
}

// ---------------------------------------------------------------------------
static void launch_gemm(const float* A, const float* B, const float* bias, float* C,
                        int M, int N, int K, int lda, int ldb, int ldc,
                        long sAb, long sBb, long sCb, int batches, int relu)
{
    dim3 grid(N / BN, M / BM, batches);
    gemm_tc<<<grid, 256, GEMM_SMEM_BYTES>>>(A, B, bias, C, K, lda, ldb, ldc,
                                            sAb, sBb, sCb, relu);
}

extern "C" void kernel_launch(void* const* d_in, const int* in_sizes, int n_in,
                              void* d_out, int out_size)
{
    const int*   hyper = (const int*)  d_in[0];
    const float* HT    = (const float*)d_in[1];
    const float* emb   = (const float*)d_in[2];
    const float* Wg1   = (const float*)d_in[3];
    const float* bg1   = (const float*)d_in[4];
    const float* Wg2   = (const float*)d_in[5];
    const float* bg2   = (const float*)d_in[6];
    const float* Wqkv  = (const float*)d_in[7];
    const float* bqkv  = (const float*)d_in[8];
    const float* Wo    = (const float*)d_in[9];
    const float* bo    = (const float*)d_in[10];
    const float* ln1g  = (const float*)d_in[11];
    const float* ln1b  = (const float*)d_in[12];
    const float* Wff1  = (const float*)d_in[13];
    const float* bff1  = (const float*)d_in[14];
    const float* Wff2  = (const float*)d_in[15];
    const float* bff2  = (const float*)d_in[16];
    const float* ln2g  = (const float*)d_in[17];
    const float* ln2b  = (const float*)d_in[18];
    const float* fc1W  = (const float*)d_in[19];
    const float* fc1b  = (const float*)d_in[20];

    float *h0, *t, *x, *x1, *qkv, *ctx, *ff, *mean, *w1p, *b1p, *w2p;
    cudaGetSymbolAddress((void**)&h0,   g_h0);
    cudaGetSymbolAddress((void**)&t,    g_t);
    cudaGetSymbolAddress((void**)&x,    g_x);
    cudaGetSymbolAddress((void**)&x1,   g_x1);
    cudaGetSymbolAddress((void**)&qkv,  g_qkv);
    cudaGetSymbolAddress((void**)&ctx,  g_ctx);
    cudaGetSymbolAddress((void**)&ff,   g_ff);
    cudaGetSymbolAddress((void**)&mean, g_mean);
    cudaGetSymbolAddress((void**)&w1p,  g_w1p);
    cudaGetSymbolAddress((void**)&b1p,  g_b1p);
    cudaGetSymbolAddress((void**)&w2p,  g_w2p);

    cudaFuncSetAttribute(flash_k, cudaFuncAttributeMaxDynamicSharedMemorySize,
                         FLASH_SMEM_BYTES);
    cudaFuncSetAttribute(gemm_tc, cudaFuncAttributeMaxDynamicSharedMemorySize,
                         GEMM_SMEM_BYTES);

    // 0. pad FF weights
    pad_w1_k<<<HID * FFP / 256, 256>>>(Wff1, w1p);
    pad_b1_k<<<2, 256>>>(bff1, b1p);
    pad_w2_k<<<FFP * HID / 256, 256>>>(Wff2, w2p);

    // 1. embedding gather
    gather_k<<<TOKENS, 64>>>(hyper, emb, h0);

    // 2. t = h0 @ Wg1
    launch_gemm(h0, Wg1, nullptr, t, TOKENS, HID, HID, HID, HID, HID, 0, 0, 0, 1, 0);

    // 3. x = batched HT @ t + bg1
    launch_gemm(HT, t, bg1, x, SEQ, HID, SEQ, SEQ, HID, HID,
                (long)SEQ * SEQ, (long)SEQ * HID, (long)SEQ * HID, NB, 0);

    // 4. t = x @ Wg2
    launch_gemm(x, Wg2, nullptr, t, TOKENS, HID, HID, HID, HID, HID, 0, 0, 0, 1, 0);

    // 5. x = batched HT @ t + bg2
    launch_gemm(HT, t, bg2, x, SEQ, HID, SEQ, SEQ, HID, HID,
                (long)SEQ * SEQ, (long)SEQ * HID, (long)SEQ * HID, NB, 0);

    // 6. qkv = x @ Wqkv + bqkv
    launch_gemm(x, Wqkv, bqkv, qkv, TOKENS, 3 * HID, HID, HID, 3 * HID, 3 * HID,
                0, 0, 0, 1, 0);

    // 7. fused flash attention per segment
    flash_k<<<dim3(4, NB * NHEADS), 256, FLASH_SMEM_BYTES>>>(qkv, ctx, 0, 512);
    flash_k<<<dim3(2, NB * NHEADS), 256, FLASH_SMEM_BYTES>>>(qkv, ctx, 512, 256);
    flash_k<<<dim3(2, NB * NHEADS), 256, FLASH_SMEM_BYTES>>>(qkv, ctx, 768, 256);

    // 8. t = ctx @ Wo + bo
    launch_gemm(ctx, Wo, bo, t, TOKENS, HID, HID, HID, HID, HID, 0, 0, 0, 1, 0);

    // 9. x1 = LN1(x + t)
    add_ln_k<<<TOKENS, 256>>>(x, t, ln1g, ln1b, x1);

    // 10. ff = relu(x1 @ w1p + b1p)   (padded to 512)
    launch_gemm(x1, w1p, b1p, ff, TOKENS, FFP, HID, HID, FFP, FFP, 0, 0, 0, 1, 1);

    // 11. t = ff @ w2p + bff2   (K padded to 512; pad cols are zero)
    launch_gemm(ff, w2p, bff2, t, TOKENS, HID, FFP, FFP, HID, HID, 0, 0, 0, 1, 0);

    // 12. x = LN2(x1 + t)
    add_ln_k<<<TOKENS, 256>>>(x1, t, ln2g, ln2b, x);

    // 13. per-segment means
    mean_k<<<NB * 3, 256>>>(x, mean);

    // 14. out = relu((p - n + f) @ fc1W + fc1b)
    final_k<<<NB, 256>>>(mean, fc1W, fc1b, (float*)d_out);
}

// round 5
// speedup vs baseline: 2.6681x; 1.1244x over previous
#include <cuda_runtime.h>
#include <cuda_bf16.h>
#include <mma.h>

using namespace nvcuda;

// ---------------------------------------------------------------------------
// GraphEncoder: tf32 TC GEMM (256x128 CTA, 64x64 warp tiles) + flash attention.
// Shapes: B=16, S=1024 (segments 512/256/256), H=256, heads=4 (Dh=64), F=400.
// ---------------------------------------------------------------------------

#define NB 16
#define SEQ 1024
#define HID 256
#define NHEADS 4
#define DH 64
#define FFP 512
#define TOKENS (NB * SEQ)

// -------------------- scratch (device globals; no allocation) --------------
__device__ float g_h0[TOKENS * HID];
__device__ float g_t[TOKENS * HID];
__device__ float g_x[TOKENS * HID];
__device__ float g_x1[TOKENS * HID];
__device__ float g_qkv[TOKENS * 3 * HID];
__device__ float g_ctx[TOKENS * HID];
__device__ float g_ff[TOKENS * FFP];
__device__ float g_mean[NB * 3 * HID];
__device__ float g_w1p[HID * FFP];
__device__ float g_b1p[FFP];
__device__ float g_w2p[FFP * HID];

// -------------------- tf32 tensor-core GEMM --------------------------------
// C[m,n] = sum_k A[m,k]*B[k,n] + bias[n] (relu?)
// Call-site guarantees: M % 256 == 0, N % 128 == 0, K % 16 == 0.
#define BM 256
#define BN 128
#define BK 16
#define APAD 20
#define BPAD 132
#define AS_STAGE (BM * APAD)                  // 5120 floats
#define BS_STAGE (BK * BPAD)                  // 2112 floats
#define STAGES 3
#define BIAS_OFF (STAGES * (AS_STAGE + BS_STAGE))          // 21696
#define GEMM_SMEM_BYTES ((BIAS_OFF + 16 * BPAD) * 4)       // 95232 B

__device__ __forceinline__ unsigned sptr(const void* p) {
    return (unsigned)__cvta_generic_to_shared(p);
}
#define CPA16(dst, src) asm volatile("cp.async.ca.shared.global [%0], [%1], 16;" :: "r"(dst), "l"(src))
#define CPA_COMMIT()    asm volatile("cp.async.commit_group;")
#define CPA_WAIT1()     asm volatile("cp.async.wait_group 1;")

__global__ void __launch_bounds__(256, 1) gemm_tc(
    const float* __restrict__ A, const float* __restrict__ Bm,
    const float* __restrict__ bias, float* __restrict__ C,
    int K, int lda, int ldb, int ldc,
    long sAb, long sBb, long sCb, int relu)
{
    extern __shared__ float sm[];

    const int z = blockIdx.z;
    A  += (long)z * sAb;
    Bm += (long)z * sBb;
    C  += (long)z * sCb;

    const int tid = threadIdx.x;
    const int w = tid >> 5;
    const int wm = w & 3, wn = w >> 2;          // 4 x 2 warps, 64x64 tiles
    const int rowTile = blockIdx.y * BM;
    const int colTile = blockIdx.x * BN;

    auto loadA = [&](int kt, int s) {
        const float* Ag = A + (long)rowTile * lda + kt * BK;
        float* sa = sm + s * AS_STAGE;
#pragma unroll
        for (int i = 0; i < 4; i++) {
            int idx = tid + i * 256;            // 1024 float4: 256 rows x 4
            int r = idx >> 2, c4 = (idx & 3) * 4;
            CPA16(sptr(sa + r * APAD + c4), Ag + (long)r * lda + c4);
        }
    };
    auto loadB = [&](int kt, int s) {
        const float* Bg = Bm + (long)(kt * BK) * ldb + colTile;
        float* sb = sm + STAGES * AS_STAGE + s * BS_STAGE;
#pragma unroll
        for (int i = 0; i < 2; i++) {
            int idx = tid + i * 256;            // 512 float4: 16 rows x 32
            int r = idx >> 5, c4 = (idx & 31) * 4;
            CPA16(sptr(sb + r * BPAD + c4), Bg + (long)r * ldb + c4);
        }
    };

    float* biasm = sm + BIAS_OFF;
    if (bias) {
        for (int i = tid; i < 16 * 128; i += 256) {
            int r = i >> 7, c = i & 127;
            biasm[r * BPAD + c] = bias[colTile + c];
        }
    }

    loadA(0, 0); loadB(0, 0); CPA_COMMIT();
    loadA(1, 1); loadB(1, 1); CPA_COMMIT();
    __syncthreads();   // biasm visible

    wmma::fragment<wmma::accumulator, 16, 16, 8, float> acc[4][4];
    if (bias) {
#pragma unroll
        for (int ni = 0; ni < 4; ni++) {
            wmma::load_matrix_sync(acc[0][ni], biasm + wn * 64 + ni * 16, BPAD,
                                   wmma::mem_row_major);
#pragma unroll
            for (int mi = 1; mi < 4; mi++) acc[mi][ni] = acc[0][ni];
        }
    } else {
#pragma unroll
        for (int mi = 0; mi < 4; mi++)
#pragma unroll
            for (int ni = 0; ni < 4; ni++) wmma::fill_fragment(acc[mi][ni], 0.f);
    }

    const int nk = K / BK;
    for (int kt = 0; kt < nk; kt++) {
        CPA_WAIT1();
        __syncthreads();
        if (kt + 2 < nk) { int s = (kt + 2) % STAGES; loadA(kt + 2, s); loadB(kt + 2, s); CPA_COMMIT(); }

        const float* sa = sm + (kt % STAGES) * AS_STAGE;
        const float* sb = sm + STAGES * AS_STAGE + (kt % STAGES) * BS_STAGE;

#pragma unroll
        for (int ks = 0; ks < 2; ks++) {
            wmma::fragment<wmma::matrix_a, 16, 16, 8, wmma::precision::tf32, wmma::row_major> af[4];
#pragma unroll
            for (int mi = 0; mi < 4; mi++)
                wmma::load_matrix_sync(af[mi], sa + (wm * 64 + mi * 16) * APAD + ks * 8, APAD);
            wmma::fragment<wmma::matrix_b, 16, 16, 8, wmma::precision::tf32, wmma::row_major> bf[4];
#pragma unroll
            for (int ni = 0; ni < 4; ni++)
                wmma::load_matrix_sync(bf[ni], sb + (ks * 8) * BPAD + wn * 64 + ni * 16, BPAD);
#pragma unroll
            for (int mi = 0; mi < 4; mi++)
#pragma unroll
                for (int ni = 0; ni < 4; ni++)
                    wmma::mma_sync(acc[mi][ni], af[mi], bf[ni], acc[mi][ni]);
        }
    }

#pragma unroll
    for (int mi = 0; mi < 4; mi++)
#pragma unroll
        for (int ni = 0; ni < 4; ni++) {
            if (relu)
#pragma unroll
                for (int e = 0; e < acc[mi][ni].num_elements; e++)
                    acc[mi][ni].x[e] = fmaxf(acc[mi][ni].x[e], 0.f);
            wmma::store_matrix_sync(
                C + (long)(rowTile + wm * 64 + mi * 16) * ldc + colTile + wn * 64 + ni * 16,
                acc[mi][ni], ldc, wmma::mem_row_major);
        }
}

// -------------------- fused flash attention --------------------------------
#define QLD 68
#define SLD 132
#define FS_Q 0
#define FS_K 8704
#define FS_V 17408
#define FS_O 26112
#define FS_S 34816
#define FS_AL 51712
#define FS_M 51840
#define FS_L 51968
#define FLASH_SMEM_BYTES ((51968 + 128) * 4)

__global__ void __launch_bounds__(256) flash_k(
    const float* __restrict__ qkv, float* __restrict__ ctx, int segOff, int L)
{
    extern __shared__ float sm[];
    float* sQ = sm + FS_Q;
    float* sK = sm + FS_K;
    float* sV = sm + FS_V;
    float* sO = sm + FS_O;
    float* sS = sm + FS_S;
    float* al = sm + FS_AL;
    float* mrow = sm + FS_M;
    float* lrow = sm + FS_L;

    const int bh = blockIdx.y;
    const int b = bh >> 2, h = bh & 3;
    const int qt = blockIdx.x;
    const int tid = threadIdx.x;
    const int w = tid >> 5;
    const int wm = w & 3, wn = w >> 2;

    const float* base = qkv + ((long)b * SEQ + segOff) * 768 + h * 64;
    const float* Qg = base + (long)qt * 128 * 768;

#pragma unroll
    for (int i = 0; i < 8; i++) {
        int idx = tid + i * 256;
        int r = idx >> 4, c4 = (idx & 15) * 4;
        *(float4*)(sQ + r * QLD + c4) = *(const float4*)(Qg + (long)r * 768 + c4);
        *(float4*)(sO + r * QLD + c4) = make_float4(0.f, 0.f, 0.f, 0.f);
    }
    if (tid < 128) { mrow[tid] = -1e30f; lrow[tid] = 0.f; }
    __syncthreads();

    const int nt = L >> 7;
    for (int t = 0; t < nt; t++) {
        const float* Kg = base + 256 + (long)t * 128 * 768;
        const float* Vg = base + 512 + (long)t * 128 * 768;
#pragma unroll
        for (int i = 0; i < 8; i++) {
            int idx = tid + i * 256;
            int r = idx >> 4, c4 = (idx & 15) * 4;
            *(float4*)(sK + r * QLD + c4) = *(const float4*)(Kg + (long)r * 768 + c4);
            *(float4*)(sV + r * QLD + c4) = *(const float4*)(Vg + (long)r * 768 + c4);
        }
        __syncthreads();

        {
            wmma::fragment<wmma::accumulator, 16, 16, 8, float> sacc[2][4];
#pragma unroll
            for (int mi = 0; mi < 2; mi++)
#pragma unroll
                for (int ni = 0; ni < 4; ni++) wmma::fill_fragment(sacc[mi][ni], 0.f);
#pragma unroll
            for (int k = 0; k < DH; k += 8) {
                wmma::fragment<wmma::matrix_a, 16, 16, 8, wmma::precision::tf32, wmma::row_major> af[2];
#pragma unroll
                for (int mi = 0; mi < 2; mi++)
                    wmma::load_matrix_sync(af[mi], sQ + (wm * 32 + mi * 16) * QLD + k, QLD);
                wmma::fragment<wmma::matrix_b, 16, 16, 8, wmma::precision::tf32, wmma::col_major> bf[4];
#pragma unroll
                for (int ni = 0; ni < 4; ni++)
                    wmma::load_matrix_sync(bf[ni], sK + (wn * 64 + ni * 16) * QLD + k, QLD);
#pragma unroll
                for (int mi = 0; mi < 2; mi++)
#pragma unroll
                    for (int ni = 0; ni < 4; ni++)
                        wmma::mma_sync(sacc[mi][ni], af[mi], bf[ni], sacc[mi][ni]);
            }
#pragma unroll
            for (int mi = 0; mi < 2; mi++)
#pragma unroll
                for (int ni = 0; ni < 4; ni++)
                    wmma::store_matrix_sync(sS + (wm * 32 + mi * 16) * SLD + wn * 64 + ni * 16,
                                            sacc[mi][ni], SLD, wmma::mem_row_major);
        }
        __syncthreads();

        {
            const int r = tid >> 1, hf = tid & 1;
            float* row = sS + r * SLD + hf * 64;
            float mx = -1e30f;
#pragma unroll 8
            for (int c = 0; c < 64; c++) mx = fmaxf(mx, row[c]);
            mx = fmaxf(mx, __shfl_xor_sync(0xffffffffu, mx, 1));
            mx *= 0.125f;
            float m_old = mrow[r];
            float m_new = fmaxf(m_old, mx);
            float a = __expf(m_old - m_new);
            float sum = 0.f;
#pragma unroll 8
            for (int c = 0; c < 64; c++) {
                float p = __expf(row[c] * 0.125f - m_new);
                row[c] = p;
                sum += p;
            }
            sum += __shfl_xor_sync(0xffffffffu, sum, 1);
            if (hf == 0) {
                mrow[r] = m_new;
                lrow[r] = lrow[r] * a + sum;
                al[r] = a;
            }
        }
        __syncthreads();

        {
            wmma::fragment<wmma::accumulator, 16, 16, 8, float> oacc[2][2];
#pragma unroll
            for (int mi = 0; mi < 2; mi++)
#pragma unroll
                for (int ni = 0; ni < 2; ni++) wmma::fill_fragment(oacc[mi][ni], 0.f);
#pragma unroll
            for (int k = 0; k < 128; k += 8) {
                wmma::fragment<wmma::matrix_a, 16, 16, 8, wmma::precision::tf32, wmma::row_major> af[2];
#pragma unroll
                for (int mi = 0; mi < 2; mi++)
                    wmma::load_matrix_sync(af[mi], sS + (wm * 32 + mi * 16) * SLD + k, SLD);
                wmma::fragment<wmma::matrix_b, 16, 16, 8, wmma::precision::tf32, wmma::row_major> bf[2];
#pragma unroll
                for (int ni = 0; ni < 2; ni++)
                    wmma::load_matrix_sync(bf[ni], sV + k * QLD + wn * 32 + ni * 16, QLD);
#pragma unroll
                for (int mi = 0; mi < 2; mi++)
#pragma unroll
                    for (int ni = 0; ni < 2; ni++)
                        wmma::mma_sync(oacc[mi][ni], af[mi], bf[ni], oacc[mi][ni]);
            }
            __syncthreads();
#pragma unroll
            for (int mi = 0; mi < 2; mi++)
#pragma unroll
                for (int ni = 0; ni < 2; ni++)
                    wmma::store_matrix_sync(sS + (wm * 32 + mi * 16) * SLD + wn * 32 + ni * 16,
                                            oacc[mi][ni], SLD, wmma::mem_row_major);
        }
        __syncthreads();

        {
            const int r = tid >> 1, hf = tid & 1;
            const float a = al[r];
            float* orow = sO + r * QLD + hf * 32;
            const float* prow = sS + r * SLD + hf * 32;
#pragma unroll 8
            for (int c = 0; c < 32; c++) orow[c] = orow[c] * a + prow[c];
        }
        __syncthreads();
    }

    float* out = ctx + ((long)b * SEQ + segOff + (long)qt * 128) * HID + h * 64;
    {
        const int r = tid >> 1, hf = tid & 1;
        const float inv = 1.f / lrow[r];
#pragma unroll
        for (int c4 = 0; c4 < 32; c4 += 4) {
            int c = hf * 32 + c4;
            float4 v = *(float4*)(sO + r * QLD + c);
            v.x *= inv; v.y *= inv; v.z *= inv; v.w *= inv;
            *(float4*)(out + (long)r * HID + c) = v;
        }
    }
}

// -------------------- small kernels -----------------------------------------
__global__ void gather_k(const int* __restrict__ idx,
                         const float* __restrict__ tab,
                         float* __restrict__ out)
{
    long tok = blockIdx.x;
    int id = idx[tok];
    const float4* src = (const float4*)(tab + (long)id * HID);
    float4* dst = (float4*)(out + tok * HID);
    dst[threadIdx.x] = src[threadIdx.x];
}

__global__ void pad_w1_k(const float* __restrict__ w, float* __restrict__ o)
{
    int i = blockIdx.x * 256 + threadIdx.x;
    int r = i >> 9, c = i & 511;
    o[i] = (c < 400) ? w[r * 400 + c] : 0.f;
}
__global__ void pad_b1_k(const float* __restrict__ b, float* __restrict__ o)
{
    int c = threadIdx.x + blockIdx.x * 256;
    o[c] = (c < 400) ? b[c] : 0.f;
}
__global__ void pad_w2_k(const float* __restrict__ w, float* __restrict__ o)
{
    int i = blockIdx.x * 256 + threadIdx.x;
    int r = i >> 8, c = i & 255;
    o[i] = (r < 400) ? w[r * 256 + c] : 0.f;
}

__global__ void add_ln_k(const float* __restrict__ x, const float* __restrict__ y,
                         const float* __restrict__ g, const float* __restrict__ b,
                         float* __restrict__ out)
{
    long row = blockIdx.x;
    int t = threadIdx.x;
    __shared__ float red[256];

    float v = x[row * HID + t] + y[row * HID + t];
    red[t] = v; __syncthreads();
    for (int s = 128; s > 0; s >>= 1) { if (t < s) red[t] += red[t + s]; __syncthreads(); }
    float mu = red[0] * (1.f / HID);
    __syncthreads();
    float d = v - mu;
    red[t] = d * d; __syncthreads();
    for (int s = 128; s > 0; s >>= 1) { if (t < s) red[t] += red[t + s]; __syncthreads(); }
    float var = red[0] * (1.f / HID);
    out[row * HID + t] = d * rsqrtf(var + 1e-5f) * g[t] + b[t];
}

__global__ void mean_k(const float* __restrict__ x, float* __restrict__ mout)
{
    int b = blockIdx.x / 3, sgi = blockIdx.x % 3;
    int off = (sgi == 0) ? 0 : (sgi == 1 ? 512 : 768);
    int L   = (sgi == 0) ? 512 : 256;
    int t = threadIdx.x;
    const float* p = x + ((long)b * SEQ + off) * HID + t;
    float s = 0.f;
    for (int i = 0; i < L; i++) s += p[(long)i * HID];
    mout[(long)blockIdx.x * HID + t] = s * (1.f / L);
}

__global__ void final_k(const float* __restrict__ mean, const float* __restrict__ W,
                        const float* __restrict__ bias, float* __restrict__ out)
{
    int b = blockIdx.x, n = threadIdx.x;
    __shared__ float comb[HID];
    const float* mp = mean + (long)b * 3 * HID;
    comb[n] = mp[n] - mp[HID + n] + mp[2 * HID + n];
    __syncthreads();
    float s = bias[n];
#pragma unroll 8
    for (int k = 0; k < HID; k++) s += comb[k] * W[k * HID + n];
    out[(long)b * HID + n] = fmaxf(s, 0.f);
}

// ---------------------------------------------------------------------------
static void launch_gemm(const float* A, const float* B, const float* bias, float* C,
                        int M, int N, int K, int lda, int ldb, int ldc,
                        long sAb, long sBb, long sCb, int batches, int relu)
{
    dim3 grid(N / BN, M / BM, batches);
    gemm_tc<<<grid, 256, GEMM_SMEM_BYTES>>>(A, B, bias, C, K, lda, ldb, ldc,
                                            sAb, sBb, sCb, relu);
}

extern "C" void kernel_launch(void* const* d_in, const int* in_sizes, int n_in,
                              void* d_out, int out_size)
{
    const int*   hyper = (const int*)  d_in[0];
    const float* HT    = (const float*)d_in[1];
    const float* emb   = (const float*)d_in[2];
    const float* Wg1   = (const float*)d_in[3];
    const float* bg1   = (const float*)d_in[4];
    const float* Wg2   = (const float*)d_in[5];
    const float* bg2   = (const float*)d_in[6];
    const float* Wqkv  = (const float*)d_in[7];
    const float* bqkv  = (const float*)d_in[8];
    const float* Wo    = (const float*)d_in[9];
    const float* bo    = (const float*)d_in[10];
    const float* ln1g  = (const float*)d_in[11];
    const float* ln1b  = (const float*)d_in[12];
    const float* Wff1  = (const float*)d_in[13];
    const float* bff1  = (const float*)d_in[14];
    const float* Wff2  = (const float*)d_in[15];
    const float* bff2  = (const float*)d_in[16];
    const float* ln2g  = (const float*)d_in[17];
    const float* ln2b  = (const float*)d_in[18];
    const float* fc1W  = (const float*)d_in[19];
    const float* fc1b  = (const float*)d_in[20];

    float *h0, *t, *x, *x1, *qkv, *ctx, *ff, *mean, *w1p, *b1p, *w2p;
    cudaGetSymbolAddress((void**)&h0,   g_h0);
    cudaGetSymbolAddress((void**)&t,    g_t);
    cudaGetSymbolAddress((void**)&x,    g_x);
    cudaGetSymbolAddress((void**)&x1,   g_x1);
    cudaGetSymbolAddress((void**)&qkv,  g_qkv);
    cudaGetSymbolAddress((void**)&ctx,  g_ctx);
    cudaGetSymbolAddress((void**)&ff,   g_ff);
    cudaGetSymbolAddress((void**)&mean, g_mean);
    cudaGetSymbolAddress((void**)&w1p,  g_w1p);
    cudaGetSymbolAddress((void**)&b1p,  g_b1p);
    cudaGetSymbolAddress((void**)&w2p,  g_w2p);

    cudaFuncSetAttribute(flash_k, cudaFuncAttributeMaxDynamicSharedMemorySize,
                         FLASH_SMEM_BYTES);
    cudaFuncSetAttribute(gemm_tc, cudaFuncAttributeMaxDynamicSharedMemorySize,
                         GEMM_SMEM_BYTES);

    // 0. pad FF weights
    pad_w1_k<<<HID * FFP / 256, 256>>>(Wff1, w1p);
    pad_b1_k<<<2, 256>>>(bff1, b1p);
    pad_w2_k<<<FFP * HID / 256, 256>>>(Wff2, w2p);

    // 1. embedding gather
    gather_k<<<TOKENS, 64>>>(hyper, emb, h0);

    // 2. t = h0 @ Wg1
    launch_gemm(h0, Wg1, nullptr, t, TOKENS, HID, HID, HID, HID, HID, 0, 0, 0, 1, 0);

    // 3. x = batched HT @ t + bg1
    launch_gemm(HT, t, bg1, x, SEQ, HID, SEQ, SEQ, HID, HID,
                (long)SEQ * SEQ, (long)SEQ * HID, (long)SEQ * HID, NB, 0);

    // 4. t = x @ Wg2
    launch_gemm(x, Wg2, nullptr, t, TOKENS, HID, HID, HID, HID, HID, 0, 0, 0, 1, 0);

    // 5. x = batched HT @ t + bg2
    launch_gemm(HT, t, bg2, x, SEQ, HID, SEQ, SEQ, HID, HID,
                (long)SEQ * SEQ, (long)SEQ * HID, (long)SEQ * HID, NB, 0);

    // 6. qkv = x @ Wqkv + bqkv
    launch_gemm(x, Wqkv, bqkv, qkv, TOKENS, 3 * HID, HID, HID, 3 * HID, 3 * HID,
                0, 0, 0, 1, 0);

    // 7. fused flash attention per segment
    flash_k<<<dim3(4, NB * NHEADS), 256, FLASH_SMEM_BYTES>>>(qkv, ctx, 0, 512);
    flash_k<<<dim3(2, NB * NHEADS), 256, FLASH_SMEM_BYTES>>>(qkv, ctx, 512, 256);
    flash_k<<<dim3(2, NB * NHEADS), 256, FLASH_SMEM_BYTES>>>(qkv, ctx, 768, 256);

    // 8. t = ctx @ Wo + bo
    launch_gemm(ctx, Wo, bo, t, TOKENS, HID, HID, HID, HID, HID, 0, 0, 0, 1, 0);

    // 9. x1 = LN1(x + t)
    add_ln_k<<<TOKENS, 256>>>(x, t, ln1g, ln1b, x1);

    // 10. ff = relu(x1 @ w1p + b1p)
    launch_gemm(x1, w1p, b1p, ff, TOKENS, FFP, HID, HID, FFP, FFP, 0, 0, 0, 1, 1);

    // 11. t = ff @ w2p + bff2
    launch_gemm(ff, w2p, bff2, t, TOKENS, HID, FFP, FFP, HID, HID, 0, 0, 0, 1, 0);

    // 12. x = LN2(x1 + t)
    add_ln_k<<<TOKENS, 256>>>(x1, t, ln2g, ln2b, x);

    // 13. per-segment means
    mean_k<<<NB * 3, 256>>>(x, mean);

    // 14. out = relu((p - n + f) @ fc1W + fc1b)
    final_k<<<NB, 256>>>(mean, fc1W, fc1b, (float*)d_out);
}

// round 6
// speedup vs baseline: 2.8793x; 1.0792x over previous
#include <cuda_runtime.h>
#include <cuda_bf16.h>
#include <mma.h>

using namespace nvcuda;

// ---------------------------------------------------------------------------
// GraphEncoder: tf32 TC GEMMs (fused gather / fused LN epilogues) + flash attn.
// Shapes: B=16, S=1024 (segments 512/256/256), H=256, heads=4 (Dh=64), F=400.
// ---------------------------------------------------------------------------

#define NB 16
#define SEQ 1024
#define HID 256
#define NHEADS 4
#define DH 64
#define FFP 512
#define TOKENS (NB * SEQ)

// -------------------- scratch (device globals; no allocation) --------------
__device__ float g_t[TOKENS * HID];
__device__ float g_x[TOKENS * HID];
__device__ float g_x1[TOKENS * HID];
__device__ float g_qkv[TOKENS * 3 * HID];
__device__ float g_ctx[TOKENS * HID];
__device__ float g_ff[TOKENS * FFP];
__device__ float g_mean[NB * 3 * HID];
__device__ float g_w1p[HID * FFP];
__device__ float g_b1p[FFP];
__device__ float g_w2p[FFP * HID];

__device__ __forceinline__ unsigned sptr(const void* p) {
    return (unsigned)__cvta_generic_to_shared(p);
}
#define CPA16(dst, src) asm volatile("cp.async.ca.shared.global [%0], [%1], 16;" :: "r"(dst), "l"(src))
#define CPA_COMMIT()    asm volatile("cp.async.commit_group;")
#define CPA_WAIT1()     asm volatile("cp.async.wait_group 1;")

// -------------------- generic tf32 GEMM (256x128 CTA) ----------------------
// C = A@B + bias (relu?), optional row-gather on A via aidx.
// M % 256 == 0, N % 128 == 0, K % 16 == 0.
#define BM 256
#define BN 128
#define BK 16
#define APAD 20
#define BPAD 132
#define AS_STAGE (BM * APAD)
#define BS_STAGE (BK * BPAD)
#define STAGES 3
#define BIAS_OFF (STAGES * (AS_STAGE + BS_STAGE))
#define GEMM_SMEM_BYTES ((BIAS_OFF + 16 * BPAD) * 4)

__global__ void __launch_bounds__(256, 1) gemm_tc(
    const float* __restrict__ A, const float* __restrict__ Bm,
    const float* __restrict__ bias, float* __restrict__ C,
    int K, int lda, int ldb, int ldc,
    long sAb, long sBb, long sCb, int relu, const int* __restrict__ aidx)
{
    extern __shared__ float sm[];

    const int z = blockIdx.z;
    A  += (long)z * sAb;
    Bm += (long)z * sBb;
    C  += (long)z * sCb;

    const int tid = threadIdx.x;
    const int w = tid >> 5;
    const int wm = w & 3, wn = w >> 2;          // 4 x 2 warps, 64x64 tiles
    const int rowTile = blockIdx.y * BM;
    const int colTile = blockIdx.x * BN;

    auto loadA = [&](int kt, int s) {
        float* sa = sm + s * AS_STAGE;
        if (aidx) {
#pragma unroll
            for (int i = 0; i < 4; i++) {
                int idx = tid + i * 256;
                int r = idx >> 2, c4 = (idx & 3) * 4;
                long row = aidx[rowTile + r];
                CPA16(sptr(sa + r * APAD + c4), A + row * lda + kt * BK + c4);
            }
        } else {
            const float* Ag = A + (long)rowTile * lda + kt * BK;
#pragma unroll
            for (int i = 0; i < 4; i++) {
                int idx = tid + i * 256;
                int r = idx >> 2, c4 = (idx & 3) * 4;
                CPA16(sptr(sa + r * APAD + c4), Ag + (long)r * lda + c4);
            }
        }
    };
    auto loadB = [&](int kt, int s) {
        const float* Bg = Bm + (long)(kt * BK) * ldb + colTile;
        float* sb = sm + STAGES * AS_STAGE + s * BS_STAGE;
#pragma unroll
        for (int i = 0; i < 2; i++) {
            int idx = tid + i * 256;
            int r = idx >> 5, c4 = (idx & 31) * 4;
            CPA16(sptr(sb + r * BPAD + c4), Bg + (long)r * ldb + c4);
        }
    };

    float* biasm = sm + BIAS_OFF;
    if (bias) {
        for (int i = tid; i < 16 * 128; i += 256) {
            int r = i >> 7, c = i & 127;
            biasm[r * BPAD + c] = bias[colTile + c];
        }
    }

    loadA(0, 0); loadB(0, 0); CPA_COMMIT();
    loadA(1, 1); loadB(1, 1); CPA_COMMIT();
    __syncthreads();

    wmma::fragment<wmma::accumulator, 16, 16, 8, float> acc[4][4];
    if (bias) {
#pragma unroll
        for (int ni = 0; ni < 4; ni++) {
            wmma::load_matrix_sync(acc[0][ni], biasm + wn * 64 + ni * 16, BPAD,
                                   wmma::mem_row_major);
#pragma unroll
            for (int mi = 1; mi < 4; mi++) acc[mi][ni] = acc[0][ni];
        }
    } else {
#pragma unroll
        for (int mi = 0; mi < 4; mi++)
#pragma unroll
            for (int ni = 0; ni < 4; ni++) wmma::fill_fragment(acc[mi][ni], 0.f);
    }

    const int nk = K / BK;
    for (int kt = 0; kt < nk; kt++) {
        CPA_WAIT1();
        __syncthreads();
        if (kt + 2 < nk) { int s = (kt + 2) % STAGES; loadA(kt + 2, s); loadB(kt + 2, s); CPA_COMMIT(); }

        const float* sa = sm + (kt % STAGES) * AS_STAGE;
        const float* sb = sm + STAGES * AS_STAGE + (kt % STAGES) * BS_STAGE;

#pragma unroll
        for (int ks = 0; ks < 2; ks++) {
            wmma::fragment<wmma::matrix_a, 16, 16, 8, wmma::precision::tf32, wmma::row_major> af[4];
#pragma unroll
            for (int mi = 0; mi < 4; mi++)
                wmma::load_matrix_sync(af[mi], sa + (wm * 64 + mi * 16) * APAD + ks * 8, APAD);
            wmma::fragment<wmma::matrix_b, 16, 16, 8, wmma::precision::tf32, wmma::row_major> bf[4];
#pragma unroll
            for (int ni = 0; ni < 4; ni++)
                wmma::load_matrix_sync(bf[ni], sb + (ks * 8) * BPAD + wn * 64 + ni * 16, BPAD);
#pragma unroll
            for (int mi = 0; mi < 4; mi++)
#pragma unroll
                for (int ni = 0; ni < 4; ni++)
                    wmma::mma_sync(acc[mi][ni], af[mi], bf[ni], acc[mi][ni]);
        }
    }

#pragma unroll
    for (int mi = 0; mi < 4; mi++)
#pragma unroll
        for (int ni = 0; ni < 4; ni++) {
            if (relu)
#pragma unroll
                for (int e = 0; e < acc[mi][ni].num_elements; e++)
                    acc[mi][ni].x[e] = fmaxf(acc[mi][ni].x[e], 0.f);
            wmma::store_matrix_sync(
                C + (long)(rowTile + wm * 64 + mi * 16) * ldc + colTile + wn * 64 + ni * 16,
                acc[mi][ni], ldc, wmma::mem_row_major);
        }
}

// -------------------- GEMM + residual + LayerNorm fused --------------------
// out = LN(res + A@B + bias)   with N == 256 (one CTA per 128-row strip).
// M % 128 == 0, K % 16 == 0.
#define LBM 128
#define LBN 256
#define LAPAD 20
#define LBPAD 260
#define LAS_STAGE (LBM * LAPAD)                 // 2560
#define LBS_STAGE (BK * LBPAD)                  // 4160
#define LEPI_OFF (STAGES * (LAS_STAGE + LBS_STAGE))   // 20160
#define LN_SMEM_BYTES ((LEPI_OFF + LBM * LBPAD + 2 * LBM) * 4)  // ~214.8 KB

__global__ void __launch_bounds__(256, 1) gemm_ln(
    const float* __restrict__ A, const float* __restrict__ Bm,
    const float* __restrict__ bias, const float* __restrict__ res,
    const float* __restrict__ lng, const float* __restrict__ lnb,
    float* __restrict__ out, int K, int lda)
{
    extern __shared__ float sm[];
    float* epi = sm + LEPI_OFF;
    float* smu = epi + LBM * LBPAD;
    float* srs = smu + LBM;

    const int tid = threadIdx.x;
    const int w = tid >> 5;
    const int wm = w & 1, wn = w >> 1;          // 2 x 4 warps, 64x64 tiles
    const int rowTile = blockIdx.x * LBM;

    auto loadA = [&](int kt, int s) {
        const float* Ag = A + (long)rowTile * lda + kt * BK;
        float* sa = sm + s * LAS_STAGE;
#pragma unroll
        for (int i = 0; i < 2; i++) {
            int idx = tid + i * 256;            // 512 f4: 128 rows x 4
            int r = idx >> 2, c4 = (idx & 3) * 4;
            CPA16(sptr(sa + r * LAPAD + c4), Ag + (long)r * lda + c4);
        }
    };
    auto loadB = [&](int kt, int s) {
        const float* Bg = Bm + (long)(kt * BK) * 256;
        float* sb = sm + STAGES * LAS_STAGE + s * LBS_STAGE;
#pragma unroll
        for (int i = 0; i < 4; i++) {
            int idx = tid + i * 256;            // 1024 f4: 16 rows x 64
            int r = idx >> 6, c4 = (idx & 63) * 4;
            CPA16(sptr(sb + r * LBPAD + c4), Bg + (long)r * 256 + c4);
        }
    };

    loadA(0, 0); loadB(0, 0); CPA_COMMIT();
    loadA(1, 1); loadB(1, 1); CPA_COMMIT();

    wmma::fragment<wmma::accumulator, 16, 16, 8, float> acc[4][4];
#pragma unroll
    for (int mi = 0; mi < 4; mi++)
#pragma unroll
        for (int ni = 0; ni < 4; ni++) wmma::fill_fragment(acc[mi][ni], 0.f);

    const int nk = K / BK;
    for (int kt = 0; kt < nk; kt++) {
        CPA_WAIT1();
        __syncthreads();
        if (kt + 2 < nk) { int s = (kt + 2) % STAGES; loadA(kt + 2, s); loadB(kt + 2, s); CPA_COMMIT(); }

        const float* sa = sm + (kt % STAGES) * LAS_STAGE;
        const float* sb = sm + STAGES * LAS_STAGE + (kt % STAGES) * LBS_STAGE;

#pragma unroll
        for (int ks = 0; ks < 2; ks++) {
            wmma::fragment<wmma::matrix_a, 16, 16, 8, wmma::precision::tf32, wmma::row_major> af[4];
#pragma unroll
            for (int mi = 0; mi < 4; mi++)
                wmma::load_matrix_sync(af[mi], sa + (wm * 64 + mi * 16) * LAPAD + ks * 8, LAPAD);
            wmma::fragment<wmma::matrix_b, 16, 16, 8, wmma::precision::tf32, wmma::row_major> bf[4];
#pragma unroll
            for (int ni = 0; ni < 4; ni++)
                wmma::load_matrix_sync(bf[ni], sb + (ks * 8) * LBPAD + wn * 64 + ni * 16, LBPAD);
#pragma unroll
            for (int mi = 0; mi < 4; mi++)
#pragma unroll
                for (int ni = 0; ni < 4; ni++)
                    wmma::mma_sync(acc[mi][ni], af[mi], bf[ni], acc[mi][ni]);
        }
    }
    __syncthreads();   // smem free for epilogue

    // stash accumulators: 128 x 256 tile
#pragma unroll
    for (int mi = 0; mi < 4; mi++)
#pragma unroll
        for (int ni = 0; ni < 4; ni++)
            wmma::store_matrix_sync(epi + (wm * 64 + mi * 16) * LBPAD + wn * 64 + ni * 16,
                                    acc[mi][ni], LBPAD, wmma::mem_row_major);
    __syncthreads();

    // val = acc + bias + res   (coalesced res read)
#pragma unroll 8
    for (int i = 0; i < 128; i++) {
        int idx = tid + i * 256;                // 32768 elements
        int r = idx >> 8, c = idx & 255;
        epi[r * LBPAD + c] += bias[c] + res[(long)(rowTile + r) * HID + c];
    }
    __syncthreads();

    // per-row stats: 2 threads per row
    {
        const int r = tid >> 1, hf = tid & 1;
        const float* row = epi + r * LBPAD + hf * 128;
        float s = 0.f, s2 = 0.f;
#pragma unroll 8
        for (int c = 0; c < 128; c++) { float v = row[c]; s += v; s2 += v * v; }
        s  += __shfl_xor_sync(0xffffffffu, s, 1);
        s2 += __shfl_xor_sync(0xffffffffu, s2, 1);
        if (hf == 0) {
            float mu = s * (1.f / 256.f);
            float var = s2 * (1.f / 256.f) - mu * mu;
            smu[r] = mu;
            srs[r] = rsqrtf(var + 1e-5f);
        }
    }
    __syncthreads();

    // write out (coalesced)
#pragma unroll 8
    for (int i = 0; i < 128; i++) {
        int idx = tid + i * 256;
        int r = idx >> 8, c = idx & 255;
        float v = (epi[r * LBPAD + c] - smu[r]) * srs[r] * lng[c] + lnb[c];
        out[(long)(rowTile + r) * HID + c] = v;
    }
}

// -------------------- fused flash attention --------------------------------
#define QLD 68
#define SLD 132
#define FS_Q 0
#define FS_K 8704
#define FS_V 17408
#define FS_O 26112
#define FS_S 34816
#define FS_AL 51712
#define FS_M 51840
#define FS_L 51968
#define FLASH_SMEM_BYTES ((51968 + 128) * 4)

__global__ void __launch_bounds__(256) flash_k(
    const float* __restrict__ qkv, float* __restrict__ ctx, int segOff, int L)
{
    extern __shared__ float sm[];
    float* sQ = sm + FS_Q;
    float* sK = sm + FS_K;
    float* sV = sm + FS_V;
    float* sO = sm + FS_O;
    float* sS = sm + FS_S;
    float* al = sm + FS_AL;
    float* mrow = sm + FS_M;
    float* lrow = sm + FS_L;

    const int bh = blockIdx.y;
    const int b = bh >> 2, h = bh & 3;
    const int qt = blockIdx.x;
    const int tid = threadIdx.x;
    const int w = tid >> 5;
    const int wm = w & 3, wn = w >> 2;

    const float* base = qkv + ((long)b * SEQ + segOff) * 768 + h * 64;
    const float* Qg = base + (long)qt * 128 * 768;

#pragma unroll
    for (int i = 0; i < 8; i++) {
        int idx = tid + i * 256;
        int r = idx >> 4, c4 = (idx & 15) * 4;
        *(float4*)(sQ + r * QLD + c4) = *(const float4*)(Qg + (long)r * 768 + c4);
        *(float4*)(sO + r * QLD + c4) = make_float4(0.f, 0.f, 0.f, 0.f);
    }
    if (tid < 128) { mrow[tid] = -1e30f; lrow[tid] = 0.f; }
    __syncthreads();

    const int nt = L >> 7;
    for (int t = 0; t < nt; t++) {
        const float* Kg = base + 256 + (long)t * 128 * 768;
        const float* Vg = base + 512 + (long)t * 128 * 768;
#pragma unroll
        for (int i = 0; i < 8; i++) {
            int idx = tid + i * 256;
            int r = idx >> 4, c4 = (idx & 15) * 4;
            *(float4*)(sK + r * QLD + c4) = *(const float4*)(Kg + (long)r * 768 + c4);
            *(float4*)(sV + r * QLD + c4) = *(const float4*)(Vg + (long)r * 768 + c4);
        }
        __syncthreads();

        {
            wmma::fragment<wmma::accumulator, 16, 16, 8, float> sacc[2][4];
#pragma unroll
            for (int mi = 0; mi < 2; mi++)
#pragma unroll
                for (int ni = 0; ni < 4; ni++) wmma::fill_fragment(sacc[mi][ni], 0.f);
#pragma unroll
            for (int k = 0; k < DH; k += 8) {
                wmma::fragment<wmma::matrix_a, 16, 16, 8, wmma::precision::tf32, wmma::row_major> af[2];
#pragma unroll
                for (int mi = 0; mi < 2; mi++)
                    wmma::load_matrix_sync(af[mi], sQ + (wm * 32 + mi * 16) * QLD + k, QLD);
                wmma::fragment<wmma::matrix_b, 16, 16, 8, wmma::precision::tf32, wmma::col_major> bf[4];
#pragma unroll
                for (int ni = 0; ni < 4; ni++)
                    wmma::load_matrix_sync(bf[ni], sK + (wn * 64 + ni * 16) * QLD + k, QLD);
#pragma unroll
                for (int mi = 0; mi < 2; mi++)
#pragma unroll
                    for (int ni = 0; ni < 4; ni++)
                        wmma::mma_sync(sacc[mi][ni], af[mi], bf[ni], sacc[mi][ni]);
            }
#pragma unroll
            for (int mi = 0; mi < 2; mi++)
#pragma unroll
                for (int ni = 0; ni < 4; ni++)
                    wmma::store_matrix_sync(sS + (wm * 32 + mi * 16) * SLD + wn * 64 + ni * 16,
                                            sacc[mi][ni], SLD, wmma::mem_row_major);
        }
        __syncthreads();

        {
            const int r = tid >> 1, hf = tid & 1;
            float* row = sS + r * SLD + hf * 64;
            float mx = -1e30f;
#pragma unroll 8
            for (int c = 0; c < 64; c++) mx = fmaxf(mx, row[c]);
            mx = fmaxf(mx, __shfl_xor_sync(0xffffffffu, mx, 1));
            mx *= 0.125f;
            float m_old = mrow[r];
            float m_new = fmaxf(m_old, mx);
            float a = __expf(m_old - m_new);
            float sum = 0.f;
#pragma unroll 8
            for (int c = 0; c < 64; c++) {
                float p = __expf(row[c] * 0.125f - m_new);
                row[c] = p;
                sum += p;
            }
            sum += __shfl_xor_sync(0xffffffffu, sum, 1);
            if (hf == 0) {
                mrow[r] = m_new;
                lrow[r] = lrow[r] * a + sum;
                al[r] = a;
            }
        }
        __syncthreads();

        {
            wmma::fragment<wmma::accumulator, 16, 16, 8, float> oacc[2][2];
#pragma unroll
            for (int mi = 0; mi < 2; mi++)
#pragma unroll
                for (int ni = 0; ni < 2; ni++) wmma::fill_fragment(oacc[mi][ni], 0.f);
#pragma unroll
            for (int k = 0; k < 128; k += 8) {
                wmma::fragment<wmma::matrix_a, 16, 16, 8, wmma::precision::tf32, wmma::row_major> af[2];
#pragma unroll
                for (int mi = 0; mi < 2; mi++)
                    wmma::load_matrix_sync(af[mi], sS + (wm * 32 + mi * 16) * SLD + k, SLD);
                wmma::fragment<wmma::matrix_b, 16, 16, 8, wmma::precision::tf32, wmma::row_major> bf[2];
#pragma unroll
                for (int ni = 0; ni < 2; ni++)
                    wmma::load_matrix_sync(bf[ni], sV + k * QLD + wn * 32 + ni * 16, QLD);
#pragma unroll
                for (int mi = 0; mi < 2; mi++)
#pragma unroll
                    for (int ni = 0; ni < 2; ni++)
                        wmma::mma_sync(oacc[mi][ni], af[mi], bf[ni], oacc[mi][ni]);
            }
            __syncthreads();
#pragma unroll
            for (int mi = 0; mi < 2; mi++)
#pragma unroll
                for (int ni = 0; ni < 2; ni++)
                    wmma::store_matrix_sync(sS + (wm * 32 + mi * 16) * SLD + wn * 32 + ni * 16,
                                            oacc[mi][ni], SLD, wmma::mem_row_major);
        }
        __syncthreads();

        {
            const int r = tid >> 1, hf = tid & 1;
            const float a = al[r];
            float* orow = sO + r * QLD + hf * 32;
            const float* prow = sS + r * SLD + hf * 32;
#pragma unroll 8
            for (int c = 0; c < 32; c++) orow[c] = orow[c] * a + prow[c];
        }
        __syncthreads();
    }

    float* out = ctx + ((long)b * SEQ + segOff + (long)qt * 128) * HID + h * 64;
    {
        const int r = tid >> 1, hf = tid & 1;
        const float inv = 1.f / lrow[r];
#pragma unroll
        for (int c4 = 0; c4 < 32; c4 += 4) {
            int c = hf * 32 + c4;
            float4 v = *(float4*)(sO + r * QLD + c);
            v.x *= inv; v.y *= inv; v.z *= inv; v.w *= inv;
            *(float4*)(out + (long)r * HID + c) = v;
        }
    }
}

// -------------------- small kernels -----------------------------------------
__global__ void pad_w1_k(const float* __restrict__ w, float* __restrict__ o)
{
    int i = blockIdx.x * 256 + threadIdx.x;
    int r = i >> 9, c = i & 511;
    o[i] = (c < 400) ? w[r * 400 + c] : 0.f;
}
__global__ void pad_b1_k(const float* __restrict__ b, float* __restrict__ o)
{
    int c = threadIdx.x + blockIdx.x * 256;
    o[c] = (c < 400) ? b[c] : 0.f;
}
__global__ void pad_w2_k(const float* __restrict__ w, float* __restrict__ o)
{
    int i = blockIdx.x * 256 + threadIdx.x;
    int r = i >> 8, c = i & 255;
    o[i] = (r < 400) ? w[r * 256 + c] : 0.f;
}

__global__ void zero_mean_k(float* __restrict__ m)
{
    m[blockIdx.x * 256 + threadIdx.x] = 0.f;
}

// partial segment sums: grid (48, 8); atomicAdd into mean (raw sums)
__global__ void mean_part_k(const float* __restrict__ x, float* __restrict__ mout)
{
    int seg = blockIdx.x, part = blockIdx.y;
    int b = seg / 3, sgi = seg % 3;
    int off = (sgi == 0) ? 0 : (sgi == 1 ? 512 : 768);
    int L   = (sgi == 0) ? 512 : 256;
    int rows = L >> 3;
    int t = threadIdx.x;
    const float* p = x + ((long)b * SEQ + off + part * rows) * HID + t;
    float s = 0.f;
    for (int i = 0; i < rows; i++) s += p[(long)i * HID];
    atomicAdd(&mout[(long)seg * HID + t], s);
}

// out = relu((p - n + f) @ W + b); mean holds raw sums
__global__ void final_k(const float* __restrict__ mean, const float* __restrict__ W,
                        const float* __restrict__ bias, float* __restrict__ out)
{
    int b = blockIdx.x, n = threadIdx.x;
    __shared__ float comb[HID];
    const float* mp = mean + (long)b * 3 * HID;
    comb[n] = mp[n] * (1.f / 512.f) - mp[HID + n] * (1.f / 256.f)
            + mp[2 * HID + n] * (1.f / 256.f);
    __syncthreads();
    float s = bias[n];
#pragma unroll 8
    for (int k = 0; k < HID; k++) s += comb[k] * W[k * HID + n];
    out[(long)b * HID + n] = fmaxf(s, 0.f);
}

// ---------------------------------------------------------------------------
static void launch_gemm(const float* A, const float* B, const float* bias, float* C,
                        int M, int N, int K, int lda, int ldb, int ldc,
                        long sAb, long sBb, long sCb, int batches, int relu,
                        const int* aidx = nullptr)
{
    dim3 grid(N / BN, M / BM, batches);
    gemm_tc<<<grid, 256, GEMM_SMEM_BYTES>>>(A, B, bias, C, K, lda, ldb, ldc,
                                            sAb, sBb, sCb, relu, aidx);
}

extern "C" void kernel_launch(void* const* d_in, const int* in_sizes, int n_in,
                              void* d_out, int out_size)
{
    const int*   hyper = (const int*)  d_in[0];
    const float* HT    = (const float*)d_in[1];
    const float* emb   = (const float*)d_in[2];
    const float* Wg1   = (const float*)d_in[3];
    const float* bg1   = (const float*)d_in[4];
    const float* Wg2   = (const float*)d_in[5];
    const float* bg2   = (const float*)d_in[6];
    const float* Wqkv  = (const float*)d_in[7];
    const float* bqkv  = (const float*)d_in[8];
    const float* Wo    = (const float*)d_in[9];
    const float* bo    = (const float*)d_in[10];
    const float* ln1g  = (const float*)d_in[11];
    const float* ln1b  = (const float*)d_in[12];
    const float* Wff1  = (const float*)d_in[13];
    const float* bff1  = (const float*)d_in[14];
    const float* Wff2  = (const float*)d_in[15];
    const float* bff2  = (const float*)d_in[16];
    const float* ln2g  = (const float*)d_in[17];
    const float* ln2b  = (const float*)d_in[18];
    const float* fc1W  = (const float*)d_in[19];
    const float* fc1b  = (const float*)d_in[20];

    float *t, *x, *x1, *qkv, *ctx, *ff, *mean, *w1p, *b1p, *w2p;
    cudaGetSymbolAddress((void**)&t,    g_t);
    cudaGetSymbolAddress((void**)&x,    g_x);
    cudaGetSymbolAddress((void**)&x1,   g_x1);
    cudaGetSymbolAddress((void**)&qkv,  g_qkv);
    cudaGetSymbolAddress((void**)&ctx,  g_ctx);
    cudaGetSymbolAddress((void**)&ff,   g_ff);
    cudaGetSymbolAddress((void**)&mean, g_mean);
    cudaGetSymbolAddress((void**)&w1p,  g_w1p);
    cudaGetSymbolAddress((void**)&b1p,  g_b1p);
    cudaGetSymbolAddress((void**)&w2p,  g_w2p);

    cudaFuncSetAttribute(flash_k, cudaFuncAttributeMaxDynamicSharedMemorySize,
                         FLASH_SMEM_BYTES);
    cudaFuncSetAttribute(gemm_tc, cudaFuncAttributeMaxDynamicSharedMemorySize,
                         GEMM_SMEM_BYTES);
    cudaFuncSetAttribute(gemm_ln, cudaFuncAttributeMaxDynamicSharedMemorySize,
                         LN_SMEM_BYTES);

    // 0. pad FF weights
    pad_w1_k<<<HID * FFP / 256, 256>>>(Wff1, w1p);
    pad_b1_k<<<2, 256>>>(bff1, b1p);
    pad_w2_k<<<FFP * HID / 256, 256>>>(Wff2, w2p);

    // 1. t = emb[hyper] @ Wg1   (gather fused into A-loader)
    launch_gemm(emb, Wg1, nullptr, t, TOKENS, HID, HID, HID, HID, HID,
                0, 0, 0, 1, 0, hyper);

    // 2. x = batched HT @ t + bg1
    launch_gemm(HT, t, bg1, x, SEQ, HID, SEQ, SEQ, HID, HID,
                (long)SEQ * SEQ, (long)SEQ * HID, (long)SEQ * HID, NB, 0);

    // 3. t = x @ Wg2
    launch_gemm(x, Wg2, nullptr, t, TOKENS, HID, HID, HID, HID, HID, 0, 0, 0, 1, 0);

    // 4. x = batched HT @ t + bg2
    launch_gemm(HT, t, bg2, x, SEQ, HID, SEQ, SEQ, HID, HID,
                (long)SEQ * SEQ, (long)SEQ * HID, (long)SEQ * HID, NB, 0);

    // 5. qkv = x @ Wqkv + bqkv
    launch_gemm(x, Wqkv, bqkv, qkv, TOKENS, 3 * HID, HID, HID, 3 * HID, 3 * HID,
                0, 0, 0, 1, 0);

    // 6. fused flash attention per segment
    flash_k<<<dim3(4, NB * NHEADS), 256, FLASH_SMEM_BYTES>>>(qkv, ctx, 0, 512);
    flash_k<<<dim3(2, NB * NHEADS), 256, FLASH_SMEM_BYTES>>>(qkv, ctx, 512, 256);
    flash_k<<<dim3(2, NB * NHEADS), 256, FLASH_SMEM_BYTES>>>(qkv, ctx, 768, 256);

    // 7. x1 = LN1(x + ctx @ Wo + bo)   (fused)
    gemm_ln<<<TOKENS / LBM, 256, LN_SMEM_BYTES>>>(ctx, Wo, bo, x, ln1g, ln1b,
                                                  x1, HID, HID);

    // 8. ff = relu(x1 @ w1p + b1p)
    launch_gemm(x1, w1p, b1p, ff, TOKENS, FFP, HID, HID, FFP, FFP, 0, 0, 0, 1, 1);

    // 9. x = LN2(x1 + ff @ w2p + bff2)   (fused)
    gemm_ln<<<TOKENS / LBM, 256, LN_SMEM_BYTES>>>(ff, w2p, bff2, x1, ln2g, ln2b,
                                                  x, FFP, FFP);

    // 10. segment means (two-stage)
    zero_mean_k<<<NB * 3, 256>>>(mean);
    mean_part_k<<<dim3(NB * 3, 8), 256>>>(x, mean);

    // 11. out = relu((p - n + f) @ fc1W + fc1b)
    final_k<<<NB, 256>>>(mean, fc1W, fc1b, (float*)d_out);
}